// round 4
// baseline (speedup 1.0000x reference)
#include <cuda_runtime.h>
#include <cstdint>

#define D_MODEL   768
#define KV_DIM    1536
#define NUM_HEADS 12
#define HEAD_DIM  64
#define BATCH     4
#define SEQ       2048
#define M_TOT     (BATCH * SEQ)   // 8192

// Scratch (no allocations allowed anywhere)
__device__ float g_q[M_TOT * D_MODEL];
__device__ float g_kv[M_TOT * KV_DIM];
__device__ float g_attn[M_TOT * D_MODEL];

// ---------------------------------------------------------------------------
// helpers
// ---------------------------------------------------------------------------
__device__ __forceinline__ unsigned f2tf(float f) {
    unsigned r;
    asm("cvt.rna.tf32.f32 %0, %1;" : "=r"(r) : "f"(f));
    return r;
}
__device__ __forceinline__ float f2tff(float f) {
    return __uint_as_float(f2tf(f));
}

__device__ __forceinline__ void mma_tf32(float c[4],
                                         unsigned a0, unsigned a1,
                                         unsigned a2, unsigned a3,
                                         unsigned b0, unsigned b1)
{
    asm("mma.sync.aligned.m16n8k8.row.col.f32.tf32.tf32.f32 "
        "{%0,%1,%2,%3}, {%4,%5,%6,%7}, {%8,%9}, {%0,%1,%2,%3};\n"
        : "+f"(c[0]), "+f"(c[1]), "+f"(c[2]), "+f"(c[3])
        : "r"(a0), "r"(a1), "r"(a2), "r"(a3), "r"(b0), "r"(b1));
}

__device__ __forceinline__ void cp16(unsigned saddr, const void* gptr) {
    asm volatile("cp.async.cg.shared.global [%0], [%1], 16;\n"
                 :: "r"(saddr), "l"(gptr));
}
__device__ __forceinline__ void cp_commit() {
    asm volatile("cp.async.commit_group;\n" ::: "memory");
}

// ---------------------------------------------------------------------------
// Pipelined tf32 GEMM body: C = A @ W^T + bias over one 128x128 output tile.
// cp.async double-buffered raw staging -> convert/permute pass -> mma.
// smem layout (floats):
//   rawA [2][4096]   (128x32 raw tile, stage 0/1)        [0, 8192)
//   rawB [2][4096]                                       [8192, 16384)
//   As   [4][1032]   (tf32 A-fragment permuted)          [16384, 20512)
//   Bs   [4][1028]   (tf32 B-fragment permuted)          [20512, 24624)
// ---------------------------------------------------------------------------
#define GEMM_SMEM_FLOATS 24624
#define GEMM_SMEM_BYTES  (GEMM_SMEM_FLOATS * 4)

__device__ __forceinline__ void gemm_pipe(const float* __restrict__ Ab,
                                          const float* __restrict__ Wb,
                                          const float* __restrict__ biasp,
                                          float* __restrict__ Cb,
                                          int N, int K, float* sm)
{
    float* rawA = sm;
    float* rawB = sm + 8192;
    float* As   = sm + 16384;   // kk stride 1032
    float* Bs   = sm + 20512;   // kk stride 1028

    const int tid  = threadIdx.x;
    const int lane = tid & 31;
    const int warp = tid >> 5;
    const int wm   = warp & 1;
    const int wn   = warp >> 1;

    const unsigned rawA_s = (unsigned)__cvta_generic_to_shared(rawA);
    const unsigned rawB_s = (unsigned)__cvta_generic_to_shared(rawB);

    float acc[4][4][4];
    #pragma unroll
    for (int i = 0; i < 4; i++)
        #pragma unroll
        for (int j = 0; j < 4; j++)
            #pragma unroll
            for (int r = 0; r < 4; r++) acc[i][j][r] = 0.0f;

    const int ntile = K >> 5;   // 32-wide k tiles

    // prologue: stage tile 0
    #pragma unroll
    for (int i = 0; i < 4; i++) {
        int idx = tid + i * 256;
        int row = idx >> 3;
        int c0  = (idx & 7) << 2;
        cp16(rawA_s + (row * 32 + c0) * 4, Ab + (size_t)row * K + c0);
        cp16(rawB_s + (row * 32 + c0) * 4, Wb + (size_t)row * K + c0);
    }
    cp_commit();

    for (int t = 0; t < ntile; t++) {
        const int stage = t & 1;
        if (t + 1 < ntile) {
            const int koff = (t + 1) << 5;
            const int ns   = stage ^ 1;
            #pragma unroll
            for (int i = 0; i < 4; i++) {
                int idx = tid + i * 256;
                int row = idx >> 3;
                int c0  = (idx & 7) << 2;
                cp16(rawA_s + (ns * 4096 + row * 32 + c0) * 4,
                     Ab + (size_t)row * K + koff + c0);
                cp16(rawB_s + (ns * 4096 + row * 32 + c0) * 4,
                     Wb + (size_t)row * K + koff + c0);
            }
            cp_commit();
            asm volatile("cp.async.wait_group 1;\n" ::: "memory");
        } else {
            asm volatile("cp.async.wait_group 0;\n" ::: "memory");
        }
        __syncthreads();

        // ---- convert raw[stage] -> permuted tf32 fragments ----
        #pragma unroll
        for (int i = 0; i < 4; i++) {
            int idx = tid + i * 256;
            int row = idx >> 3;
            int c0  = (idx & 7) << 2;
            float4 v = *(const float4*)&rawA[stage * 4096 + row * 32 + c0];
            int kk   = c0 >> 3;
            int cc   = c0 & 7;
            int mt   = row >> 4;
            int rr   = row & 15;
            int slot = (rr >> 3) | ((cc >> 2) << 1);
            int base = (mt * 32 + ((rr & 7) << 2)) * 4 + slot;
            float* Ak = As + kk * 1032;
            Ak[base +  0] = f2tff(v.x);
            Ak[base +  4] = f2tff(v.y);
            Ak[base +  8] = f2tff(v.z);
            Ak[base + 12] = f2tff(v.w);

            float4 w = *(const float4*)&rawB[stage * 4096 + row * 32 + c0];
            int nt   = row >> 3;
            int nn   = row & 7;
            int slt  = cc >> 2;
            int bas  = (nt * 32 + (nn << 2)) * 2 + slt;
            float* Bk = Bs + kk * 1028;
            Bk[bas + 0] = f2tff(w.x);
            Bk[bas + 2] = f2tff(w.y);
            Bk[bas + 4] = f2tff(w.z);
            Bk[bas + 6] = f2tff(w.w);
        }
        __syncthreads();

        // ---- compute ----
        #pragma unroll
        for (int kk = 0; kk < 4; kk++) {
            unsigned a[4][4], b[4][2];
            const float* Ak = As + kk * 1032;
            const float* Bk = Bs + kk * 1028;
            #pragma unroll
            for (int mt = 0; mt < 4; mt++) {
                float4 av = *(const float4*)&Ak[((wm * 4 + mt) * 32 + lane) * 4];
                a[mt][0] = __float_as_uint(av.x);
                a[mt][1] = __float_as_uint(av.y);
                a[mt][2] = __float_as_uint(av.z);
                a[mt][3] = __float_as_uint(av.w);
            }
            #pragma unroll
            for (int nt = 0; nt < 4; nt++) {
                float2 bv = *(const float2*)&Bk[((wn * 4 + nt) * 32 + lane) * 2];
                b[nt][0] = __float_as_uint(bv.x);
                b[nt][1] = __float_as_uint(bv.y);
            }
            #pragma unroll
            for (int mt = 0; mt < 4; mt++)
                #pragma unroll
                for (int nt = 0; nt < 4; nt++)
                    mma_tf32(acc[mt][nt], a[mt][0], a[mt][1], a[mt][2], a[mt][3],
                             b[nt][0], b[nt][1]);
        }
        __syncthreads();
    }

    // ---- epilogue: bias + store ----
    #pragma unroll
    for (int mt = 0; mt < 4; mt++) {
        int row = (wm * 4 + mt) * 16 + (lane >> 2);
        #pragma unroll
        for (int nt = 0; nt < 4; nt++) {
            int col = (wn * 4 + nt) * 8 + ((lane & 3) << 1);
            float2 bv = *(const float2*)(biasp + col);
            float2 r0, r1;
            r0.x = acc[mt][nt][0] + bv.x;
            r0.y = acc[mt][nt][1] + bv.y;
            r1.x = acc[mt][nt][2] + bv.x;
            r1.y = acc[mt][nt][3] + bv.y;
            *(float2*)(Cb + (size_t)row * N + col)       = r0;
            *(float2*)(Cb + (size_t)(row + 8) * N + col) = r1;
        }
    }
}

// Merged Q + KV projection: grid (18, 64). x<6 -> Q column block, else KV.
__global__ __launch_bounds__(256, 2)
void gemm_proj_qkv(const float* __restrict__ x, const float* __restrict__ y,
                   const float* __restrict__ Wq, const float* __restrict__ bq,
                   const float* __restrict__ Wkv, const float* __restrict__ bkv,
                   float* __restrict__ qout, float* __restrict__ kvout)
{
    extern __shared__ float dsm[];
    const int bx = blockIdx.x, by = blockIdx.y;
    if (bx < 6) {
        gemm_pipe(x + (size_t)by * 128 * D_MODEL,
                  Wq + (size_t)bx * 128 * D_MODEL,
                  bq + bx * 128,
                  qout + (size_t)by * 128 * D_MODEL + bx * 128,
                  D_MODEL, D_MODEL, dsm);
    } else {
        const int cx = bx - 6;
        gemm_pipe(y + (size_t)by * 128 * D_MODEL,
                  Wkv + (size_t)cx * 128 * D_MODEL,
                  bkv + cx * 128,
                  kvout + (size_t)by * 128 * KV_DIM + cx * 128,
                  KV_DIM, D_MODEL, dsm);
    }
}

__global__ __launch_bounds__(256, 2)
void gemm_single(const float* __restrict__ A, const float* __restrict__ W,
                 const float* __restrict__ bias, float* __restrict__ C,
                 int N, int K)
{
    extern __shared__ float dsm[];
    gemm_pipe(A + (size_t)blockIdx.y * 128 * K,
              W + (size_t)blockIdx.x * 128 * K,
              bias + blockIdx.x * 128,
              C + (size_t)blockIdx.y * 128 * N + blockIdx.x * 128,
              N, K, dsm);
}

// ---------------------------------------------------------------------------
// Tensor-core flash attention (tf32 mma, fp32 softmax/accum) with K/V
// register prefetch: next tile's LDGs issue before compute of current tile.
// ---------------------------------------------------------------------------
#define ATT_SMEM_BYTES (16384 * 4)

__global__ __launch_bounds__(256, 2)
void attn_tc_kernel(const float* __restrict__ q, const float* __restrict__ kv,
                    const float* __restrict__ mask, float* __restrict__ outp)
{
    extern __shared__ float sm[];
    float* Qs = sm;
    float* Ks = sm + 8192;
    float* Vs = sm + 12288;

    const int tid  = threadIdx.x;
    const int lane = tid & 31;
    const int warp = tid >> 5;
    const int qt = blockIdx.x, h = blockIdx.y, b = blockIdx.z;
    const int q0 = qt * 128;

    // ---- stage Q (scaled, tf32, A-fragment permuted) ----
    {
        const float* qbase = q + (size_t)(b * SEQ + q0) * D_MODEL + h * HEAD_DIM;
        #pragma unroll
        for (int i = 0; i < 8; i++) {
            int idx = tid + i * 256;
            int row = idx >> 4;
            int c0  = (idx & 15) << 2;
            float4 v = *(const float4*)(qbase + (size_t)row * D_MODEL + c0);
            int w  = row >> 4;
            int r  = row & 15;
            int kk = c0 >> 3;
            int j  = ((r >> 3) & 1) | ((c0 & 4) ? 2 : 0);
            int l0 = (r & 7) << 2;
            int base = ((w * 8 + kk) * 32) * 4 + j;
            Qs[base + (((l0 + 0) ^ kk) << 2)] = f2tff(v.x * 0.125f);
            Qs[base + (((l0 + 1) ^ kk) << 2)] = f2tff(v.y * 0.125f);
            Qs[base + (((l0 + 2) ^ kk) << 2)] = f2tff(v.z * 0.125f);
            Qs[base + (((l0 + 3) ^ kk) << 2)] = f2tff(v.w * 0.125f);
        }
    }

    float of[8][4];
    #pragma unroll
    for (int nt = 0; nt < 8; nt++)
        #pragma unroll
        for (int r = 0; r < 4; r++) of[nt][r] = 0.0f;
    float m0 = -1e30f, m8 = -1e30f, l0s = 0.0f, l8s = 0.0f;

    const float* kvbase = kv + (size_t)(b * SEQ) * KV_DIM + h * (2 * HEAD_DIM);
    const float* mrow0  = mask + (size_t)(q0 + warp * 16 + (lane >> 2)) * SEQ
                               + ((lane & 3) << 1);

    const int srcA = (lane & 28) | ((lane & 3) >> 1);
    const int srcB = srcA | 2;
    const bool oddl = (lane & 1);

    // per-thread staging coordinates (same every iteration)
    int kr_[4], c0_[4];
    #pragma unroll
    for (int i = 0; i < 4; i++) {
        int idx = tid + i * 256;
        kr_[i] = idx >> 4;
        c0_[i] = (idx & 15) << 2;
    }

    // prefetch tile 0
    float4 pk[4], pv[4];
    #pragma unroll
    for (int i = 0; i < 4; i++) {
        const float* kb = kvbase + (size_t)kr_[i] * KV_DIM;
        pk[i] = *(const float4*)(kb + c0_[i]);
        pv[i] = *(const float4*)(kb + HEAD_DIM + c0_[i]);
    }

    for (int kt = 0; kt < SEQ / 64; kt++) {
        const int k0 = kt * 64;

        // ---- stage K tile from prefetch regs ----
        #pragma unroll
        for (int i = 0; i < 4; i++) {
            int kr = kr_[i], c0 = c0_[i];
            float4 v = pk[i];
            int kk   = c0 >> 3;
            int nt   = kr >> 3;
            int np   = nt >> 1;
            int slot = ((nt & 1) << 1) | ((c0 >> 2) & 1);
            int l0   = (kr & 7) << 2;
            int base = ((kk * 4 + np) * 32) * 4 + slot;
            Ks[base + (((l0 + 0) ^ kk) << 2)] = f2tff(v.x);
            Ks[base + (((l0 + 1) ^ kk) << 2)] = f2tff(v.y);
            Ks[base + (((l0 + 2) ^ kk) << 2)] = f2tff(v.z);
            Ks[base + (((l0 + 3) ^ kk) << 2)] = f2tff(v.w);
        }
        // ---- stage V tile from prefetch regs ----
        #pragma unroll
        for (int i = 0; i < 4; i++) {
            int kr = kr_[i], c0 = c0_[i];
            float4 v = pv[i];
            int kk   = kr >> 3;
            int np   = c0 >> 4;
            int slot = (((c0 >> 3) & 1) << 1) | (((kr & 7) >= 4) ? 1 : 0);
            int l0   = ((c0 & 7) << 2) + (kr & 3);
            int base = ((kk * 4 + np) * 32) * 4 + slot;
            Vs[base + (((l0 +  0) ^ kk) << 2)] = f2tff(v.x);
            Vs[base + (((l0 +  4) ^ kk) << 2)] = f2tff(v.y);
            Vs[base + (((l0 +  8) ^ kk) << 2)] = f2tff(v.z);
            Vs[base + (((l0 + 12) ^ kk) << 2)] = f2tff(v.w);
        }
        __syncthreads();

        // ---- prefetch next tile (latency hidden behind compute) ----
        if (kt + 1 < SEQ / 64) {
            const float* kbn = kvbase + (size_t)(k0 + 64) * KV_DIM;
            #pragma unroll
            for (int i = 0; i < 4; i++) {
                const float* kb = kbn + (size_t)kr_[i] * KV_DIM;
                pk[i] = *(const float4*)(kb + c0_[i]);
                pv[i] = *(const float4*)(kb + HEAD_DIM + c0_[i]);
            }
        }

        // ---- S = Q K^T ----
        float sf[8][4];
        #pragma unroll
        for (int nt = 0; nt < 8; nt++)
            #pragma unroll
            for (int r = 0; r < 4; r++) sf[nt][r] = 0.0f;

        #pragma unroll
        for (int kk = 0; kk < 8; kk++) {
            float4 aq = *(const float4*)&Qs[((warp * 8 + kk) * 32 + (lane ^ kk)) * 4];
            unsigned a0 = __float_as_uint(aq.x), a1 = __float_as_uint(aq.y);
            unsigned a2 = __float_as_uint(aq.z), a3 = __float_as_uint(aq.w);
            #pragma unroll
            for (int np = 0; np < 4; np++) {
                float4 kf = *(const float4*)&Ks[((kk * 4 + np) * 32 + (lane ^ kk)) * 4];
                mma_tf32(sf[2 * np],     a0, a1, a2, a3,
                         __float_as_uint(kf.x), __float_as_uint(kf.y));
                mma_tf32(sf[2 * np + 1], a0, a1, a2, a3,
                         __float_as_uint(kf.z), __float_as_uint(kf.w));
            }
        }

        // ---- mask add ----
        #pragma unroll
        for (int nt = 0; nt < 8; nt++) {
            float2 mv0 = *(const float2*)(mrow0 + k0 + nt * 8);
            float2 mv8 = *(const float2*)(mrow0 + (size_t)8 * SEQ + k0 + nt * 8);
            sf[nt][0] += mv0.x; sf[nt][1] += mv0.y;
            sf[nt][2] += mv8.x; sf[nt][3] += mv8.y;
        }

        // ---- online softmax ----
        float mx0 = -1e30f, mx8 = -1e30f;
        #pragma unroll
        for (int nt = 0; nt < 8; nt++) {
            mx0 = fmaxf(mx0, fmaxf(sf[nt][0], sf[nt][1]));
            mx8 = fmaxf(mx8, fmaxf(sf[nt][2], sf[nt][3]));
        }
        mx0 = fmaxf(mx0, __shfl_xor_sync(0xffffffffu, mx0, 1));
        mx0 = fmaxf(mx0, __shfl_xor_sync(0xffffffffu, mx0, 2));
        mx8 = fmaxf(mx8, __shfl_xor_sync(0xffffffffu, mx8, 1));
        mx8 = fmaxf(mx8, __shfl_xor_sync(0xffffffffu, mx8, 2));

        float nm0 = fmaxf(m0, mx0), nm8 = fmaxf(m8, mx8);
        float sc0 = __expf(m0 - nm0), sc8 = __expf(m8 - nm8);
        m0 = nm0; m8 = nm8;

        float rs0 = 0.0f, rs8 = 0.0f;
        #pragma unroll
        for (int nt = 0; nt < 8; nt++) {
            sf[nt][0] = __expf(sf[nt][0] - nm0); rs0 += sf[nt][0];
            sf[nt][1] = __expf(sf[nt][1] - nm0); rs0 += sf[nt][1];
            sf[nt][2] = __expf(sf[nt][2] - nm8); rs8 += sf[nt][2];
            sf[nt][3] = __expf(sf[nt][3] - nm8); rs8 += sf[nt][3];
        }
        rs0 += __shfl_xor_sync(0xffffffffu, rs0, 1);
        rs0 += __shfl_xor_sync(0xffffffffu, rs0, 2);
        rs8 += __shfl_xor_sync(0xffffffffu, rs8, 1);
        rs8 += __shfl_xor_sync(0xffffffffu, rs8, 2);
        l0s = l0s * sc0 + rs0;
        l8s = l8s * sc8 + rs8;

        #pragma unroll
        for (int nt = 0; nt < 8; nt++) {
            of[nt][0] *= sc0; of[nt][1] *= sc0;
            of[nt][2] *= sc8; of[nt][3] *= sc8;
        }

        // ---- O += P V (C-frag -> A-frag via shuffles) ----
        #pragma unroll
        for (int kk = 0; kk < 8; kk++) {
            float p0 = sf[kk][0], p1 = sf[kk][1], p2 = sf[kk][2], p3 = sf[kk][3];
            float e0 = __shfl_sync(0xffffffffu, p0, srcA);
            float e1 = __shfl_sync(0xffffffffu, p1, srcA);
            float e2 = __shfl_sync(0xffffffffu, p2, srcA);
            float e3 = __shfl_sync(0xffffffffu, p3, srcA);
            float g0 = __shfl_sync(0xffffffffu, p0, srcB);
            float g1 = __shfl_sync(0xffffffffu, p1, srcB);
            float g2 = __shfl_sync(0xffffffffu, p2, srcB);
            float g3 = __shfl_sync(0xffffffffu, p3, srcB);
            unsigned a0 = f2tf(oddl ? e1 : e0);
            unsigned a1 = f2tf(oddl ? e3 : e2);
            unsigned a2 = f2tf(oddl ? g1 : g0);
            unsigned a3 = f2tf(oddl ? g3 : g2);
            #pragma unroll
            for (int np = 0; np < 4; np++) {
                float4 vf = *(const float4*)&Vs[((kk * 4 + np) * 32 + (lane ^ kk)) * 4];
                mma_tf32(of[2 * np],     a0, a1, a2, a3,
                         __float_as_uint(vf.x), __float_as_uint(vf.y));
                mma_tf32(of[2 * np + 1], a0, a1, a2, a3,
                         __float_as_uint(vf.z), __float_as_uint(vf.w));
            }
        }
        __syncthreads();
    }

    // ---- normalize + store ----
    float inv0 = 1.0f / l0s, inv8 = 1.0f / l8s;
    float* obase = outp + (size_t)(b * SEQ + q0 + warp * 16 + (lane >> 2)) * D_MODEL
                        + h * HEAD_DIM + ((lane & 3) << 1);
    #pragma unroll
    for (int nt = 0; nt < 8; nt++) {
        float2 r0 = make_float2(of[nt][0] * inv0, of[nt][1] * inv0);
        float2 r8 = make_float2(of[nt][2] * inv8, of[nt][3] * inv8);
        *(float2*)(obase + nt * 8)                       = r0;
        *(float2*)(obase + (size_t)8 * D_MODEL + nt * 8) = r8;
    }
}

// ---------------------------------------------------------------------------
extern "C" void kernel_launch(void* const* d_in, const int* in_sizes, int n_in,
                              void* d_out, int out_size)
{
    const float* x    = (const float*)d_in[0];
    const float* y    = (const float*)d_in[1];
    const float* mask = (const float*)d_in[2];
    const float* Wq   = (const float*)d_in[3];
    const float* bq   = (const float*)d_in[4];
    const float* Wkv  = (const float*)d_in[5];
    const float* bkv  = (const float*)d_in[6];
    const float* Wo   = (const float*)d_in[7];
    const float* bo   = (const float*)d_in[8];
    float* out = (float*)d_out;

    float *qp, *kvp, *attnp;
    cudaGetSymbolAddress((void**)&qp,    g_q);
    cudaGetSymbolAddress((void**)&kvp,   g_kv);
    cudaGetSymbolAddress((void**)&attnp, g_attn);

    cudaFuncSetAttribute(gemm_proj_qkv,
                         cudaFuncAttributeMaxDynamicSharedMemorySize,
                         GEMM_SMEM_BYTES);
    cudaFuncSetAttribute(gemm_single,
                         cudaFuncAttributeMaxDynamicSharedMemorySize,
                         GEMM_SMEM_BYTES);
    cudaFuncSetAttribute(attn_tc_kernel,
                         cudaFuncAttributeMaxDynamicSharedMemorySize,
                         ATT_SMEM_BYTES);

    dim3 blk(256);

    // Q and KV projections, merged
    gemm_proj_qkv<<<dim3(18, M_TOT / 128), blk, GEMM_SMEM_BYTES>>>(
        x, y, Wq, bq, Wkv, bkv, qp, kvp);
    // attention
    attn_tc_kernel<<<dim3(SEQ / 128, NUM_HEADS, BATCH), blk, ATT_SMEM_BYTES>>>(
        qp, kvp, mask, attnp);
    // out = attn @ Wo^T + bo
    gemm_single<<<dim3(D_MODEL / 128, M_TOT / 128), blk, GEMM_SMEM_BYTES>>>(
        attnp, Wo, bo, out, D_MODEL, D_MODEL);
}

// round 5
// speedup vs baseline: 1.1434x; 1.1434x over previous
#include <cuda_runtime.h>
#include <cstdint>

#define D_MODEL   768
#define KV_DIM    1536
#define NUM_HEADS 12
#define HEAD_DIM  64
#define BATCH     4
#define SEQ       2048
#define M_TOT     (BATCH * SEQ)   // 8192

// Scratch (no allocations allowed anywhere)
__device__ float g_q[M_TOT * D_MODEL];
__device__ float g_kv[M_TOT * KV_DIM];
__device__ float g_attn[M_TOT * D_MODEL];

// ---------------------------------------------------------------------------
// helpers
// ---------------------------------------------------------------------------
__device__ __forceinline__ unsigned f2tf(float f) {
    unsigned r;
    asm("cvt.rna.tf32.f32 %0, %1;" : "=r"(r) : "f"(f));
    return r;
}
__device__ __forceinline__ float f2tff(float f) {
    return __uint_as_float(f2tf(f));
}
__device__ __forceinline__ unsigned u2tf(unsigned u) {
    unsigned r;
    asm("cvt.rna.tf32.f32 %0, %1;" : "=r"(r) : "f"(__uint_as_float(u)));
    return r;
}

__device__ __forceinline__ void mma_tf32(float c[4],
                                         unsigned a0, unsigned a1,
                                         unsigned a2, unsigned a3,
                                         unsigned b0, unsigned b1)
{
    asm("mma.sync.aligned.m16n8k8.row.col.f32.tf32.tf32.f32 "
        "{%0,%1,%2,%3}, {%4,%5,%6,%7}, {%8,%9}, {%0,%1,%2,%3};\n"
        : "+f"(c[0]), "+f"(c[1]), "+f"(c[2]), "+f"(c[3])
        : "r"(a0), "r"(a1), "r"(a2), "r"(a3), "r"(b0), "r"(b1));
}

__device__ __forceinline__ void cp16(unsigned saddr, const void* gptr) {
    asm volatile("cp.async.cg.shared.global [%0], [%1], 16;\n"
                 :: "r"(saddr), "l"(gptr));
}
__device__ __forceinline__ void cp_commit() {
    asm volatile("cp.async.commit_group;\n" ::: "memory");
}

__device__ __forceinline__ void ldsm_x4(unsigned& d0, unsigned& d1,
                                        unsigned& d2, unsigned& d3,
                                        unsigned saddr)
{
    asm volatile("ldmatrix.sync.aligned.m8n8.x4.shared.b16 {%0,%1,%2,%3}, [%4];\n"
                 : "=r"(d0), "=r"(d1), "=r"(d2), "=r"(d3) : "r"(saddr));
}

// ---------------------------------------------------------------------------
// Pipelined tf32 GEMM: C = A @ W^T + bias over one 128x128 tile.
// cp.async (swizzled raw fp32) double-buffer -> ldmatrix -> cvt.tf32 -> mma.
// Raw tile: 128 rows x 32 floats (128B row = 8 x 16B chunks).
// Swizzle: chunk' = chunk ^ (row & 7)  (applied at both write and read).
// smem: rawA[2][4096] + rawB[2][4096] floats = 64 KB.
// ---------------------------------------------------------------------------
#define GEMM_SMEM_BYTES (16384 * 4)

__device__ __forceinline__ void gemm_pipe(const float* __restrict__ Ab,
                                          const float* __restrict__ Wb,
                                          const float* __restrict__ biasp,
                                          float* __restrict__ Cb,
                                          int N, int K, float* sm)
{
    float* rawA = sm;            // [2][4096]
    float* rawB = sm + 8192;     // [2][4096]

    const int tid  = threadIdx.x;
    const int lane = tid & 31;
    const int warp = tid >> 5;
    const int wm   = warp & 1;
    const int wn   = warp >> 1;

    const unsigned rawA_s = (unsigned)__cvta_generic_to_shared(rawA);
    const unsigned rawB_s = (unsigned)__cvta_generic_to_shared(rawB);

    // staging coords (constant per thread)
    const int srow = tid >> 3;          // 0..31 (base; +32*i per chunk blk)
    const int sch  = tid & 7;           // 16B chunk within row

    float acc[4][4][4];
    #pragma unroll
    for (int i = 0; i < 4; i++)
        #pragma unroll
        for (int j = 0; j < 4; j++)
            #pragma unroll
            for (int r = 0; r < 4; r++) acc[i][j][r] = 0.0f;

    const int ntile = K >> 5;

    // ldmatrix read addresses (byte offsets within a stage)
    //  A: row = wm*64 + mt*16 + (lane&15), chunk = kk*2 + (lane>>4)
    //  B: row = wn*32 + p*16 + ((lane>>4)<<3) + (lane&7), chunk = kk*2 + ((lane>>3)&1)
    const int a_row = wm * 64 + (lane & 15);
    const int a_chv = (lane >> 4);          // 0/1 -> +k4
    const int b_row = wn * 32 + ((lane >> 4) << 3) + (lane & 7);
    const int b_chv = (lane >> 3) & 1;

    // prologue: stage tile 0
    #pragma unroll
    for (int i = 0; i < 4; i++) {
        int row = srow + i * 32;
        int sw  = sch ^ (row & 7);
        cp16(rawA_s + (row * 32 + sw * 4) * 4, Ab + (size_t)row * K + sch * 4);
        cp16(rawB_s + (row * 32 + sw * 4) * 4, Wb + (size_t)row * K + sch * 4);
    }
    cp_commit();

    for (int t = 0; t < ntile; t++) {
        const int stage = t & 1;
        if (t + 1 < ntile) {
            const int koff = (t + 1) << 5;
            const int ns   = stage ^ 1;
            #pragma unroll
            for (int i = 0; i < 4; i++) {
                int row = srow + i * 32;
                int sw  = sch ^ (row & 7);
                cp16(rawA_s + (ns * 4096 + row * 32 + sw * 4) * 4,
                     Ab + (size_t)row * K + koff + sch * 4);
                cp16(rawB_s + (ns * 4096 + row * 32 + sw * 4) * 4,
                     Wb + (size_t)row * K + koff + sch * 4);
            }
            cp_commit();
            asm volatile("cp.async.wait_group 1;\n" ::: "memory");
        } else {
            asm volatile("cp.async.wait_group 0;\n" ::: "memory");
        }
        __syncthreads();

        const unsigned baseA = rawA_s + stage * 16384;
        const unsigned baseB = rawB_s + stage * 16384;

        #pragma unroll
        for (int kk = 0; kk < 4; kk++) {
            unsigned a[4][4], b[4][2];
            #pragma unroll
            for (int mt = 0; mt < 4; mt++) {
                int row = a_row + mt * 16;
                int ch  = kk * 2 + a_chv;
                unsigned ad = baseA + row * 128 + ((ch ^ (row & 7)) << 4);
                ldsm_x4(a[mt][0], a[mt][1], a[mt][2], a[mt][3], ad);
            }
            #pragma unroll
            for (int p = 0; p < 2; p++) {
                int row = b_row + p * 16;
                int ch  = kk * 2 + b_chv;
                unsigned bd = baseB + row * 128 + ((ch ^ (row & 7)) << 4);
                ldsm_x4(b[2 * p][0], b[2 * p][1], b[2 * p + 1][0], b[2 * p + 1][1], bd);
            }
            #pragma unroll
            for (int mt = 0; mt < 4; mt++)
                #pragma unroll
                for (int r = 0; r < 4; r++) a[mt][r] = u2tf(a[mt][r]);
            #pragma unroll
            for (int nt = 0; nt < 4; nt++) {
                b[nt][0] = u2tf(b[nt][0]);
                b[nt][1] = u2tf(b[nt][1]);
            }
            #pragma unroll
            for (int mt = 0; mt < 4; mt++)
                #pragma unroll
                for (int nt = 0; nt < 4; nt++)
                    mma_tf32(acc[mt][nt], a[mt][0], a[mt][1], a[mt][2], a[mt][3],
                             b[nt][0], b[nt][1]);
        }
        __syncthreads();
    }

    // ---- epilogue: bias + store ----
    #pragma unroll
    for (int mt = 0; mt < 4; mt++) {
        int row = (wm * 4 + mt) * 16 + (lane >> 2);
        #pragma unroll
        for (int nt = 0; nt < 4; nt++) {
            int col = (wn * 4 + nt) * 8 + ((lane & 3) << 1);
            float2 bv = *(const float2*)(biasp + col);
            float2 r0, r1;
            r0.x = acc[mt][nt][0] + bv.x;
            r0.y = acc[mt][nt][1] + bv.y;
            r1.x = acc[mt][nt][2] + bv.x;
            r1.y = acc[mt][nt][3] + bv.y;
            *(float2*)(Cb + (size_t)row * N + col)       = r0;
            *(float2*)(Cb + (size_t)(row + 8) * N + col) = r1;
        }
    }
}

// Merged Q + KV projection: grid (18, 64). x<6 -> Q column block, else KV.
__global__ __launch_bounds__(256, 2)
void gemm_proj_qkv(const float* __restrict__ x, const float* __restrict__ y,
                   const float* __restrict__ Wq, const float* __restrict__ bq,
                   const float* __restrict__ Wkv, const float* __restrict__ bkv,
                   float* __restrict__ qout, float* __restrict__ kvout)
{
    extern __shared__ float dsm[];
    const int bx = blockIdx.x, by = blockIdx.y;
    if (bx < 6) {
        gemm_pipe(x + (size_t)by * 128 * D_MODEL,
                  Wq + (size_t)bx * 128 * D_MODEL,
                  bq + bx * 128,
                  qout + (size_t)by * 128 * D_MODEL + bx * 128,
                  D_MODEL, D_MODEL, dsm);
    } else {
        const int cx = bx - 6;
        gemm_pipe(y + (size_t)by * 128 * D_MODEL,
                  Wkv + (size_t)cx * 128 * D_MODEL,
                  bkv + cx * 128,
                  kvout + (size_t)by * 128 * KV_DIM + cx * 128,
                  KV_DIM, D_MODEL, dsm);
    }
}

__global__ __launch_bounds__(256, 2)
void gemm_single(const float* __restrict__ A, const float* __restrict__ W,
                 const float* __restrict__ bias, float* __restrict__ C,
                 int N, int K)
{
    extern __shared__ float dsm[];
    gemm_pipe(A + (size_t)blockIdx.y * 128 * K,
              W + (size_t)blockIdx.x * 128 * K,
              bias + blockIdx.x * 128,
              C + (size_t)blockIdx.y * 128 * N + blockIdx.x * 128,
              N, K, dsm);
}

// ---------------------------------------------------------------------------
// Tensor-core flash attention (round-3 version: no register prefetch).
// Grid: (S/128, H, B). Block: 256 threads = 8 warps.
// ---------------------------------------------------------------------------
#define ATT_SMEM_BYTES (16384 * 4)

__global__ __launch_bounds__(256, 2)
void attn_tc_kernel(const float* __restrict__ q, const float* __restrict__ kv,
                    const float* __restrict__ mask, float* __restrict__ outp)
{
    extern __shared__ float sm[];
    float* Qs = sm;
    float* Ks = sm + 8192;
    float* Vs = sm + 12288;

    const int tid  = threadIdx.x;
    const int lane = tid & 31;
    const int warp = tid >> 5;
    const int qt = blockIdx.x, h = blockIdx.y, b = blockIdx.z;
    const int q0 = qt * 128;

    // ---- stage Q (scaled, tf32, A-fragment permuted) ----
    {
        const float* qbase = q + (size_t)(b * SEQ + q0) * D_MODEL + h * HEAD_DIM;
        #pragma unroll
        for (int i = 0; i < 8; i++) {
            int idx = tid + i * 256;
            int row = idx >> 4;
            int c0  = (idx & 15) << 2;
            float4 v = *(const float4*)(qbase + (size_t)row * D_MODEL + c0);
            int w  = row >> 4;
            int r  = row & 15;
            int kk = c0 >> 3;
            int j  = ((r >> 3) & 1) | ((c0 & 4) ? 2 : 0);
            int l0 = (r & 7) << 2;
            int base = ((w * 8 + kk) * 32) * 4 + j;
            Qs[base + (((l0 + 0) ^ kk) << 2)] = f2tff(v.x * 0.125f);
            Qs[base + (((l0 + 1) ^ kk) << 2)] = f2tff(v.y * 0.125f);
            Qs[base + (((l0 + 2) ^ kk) << 2)] = f2tff(v.z * 0.125f);
            Qs[base + (((l0 + 3) ^ kk) << 2)] = f2tff(v.w * 0.125f);
        }
    }

    float of[8][4];
    #pragma unroll
    for (int nt = 0; nt < 8; nt++)
        #pragma unroll
        for (int r = 0; r < 4; r++) of[nt][r] = 0.0f;
    float m0 = -1e30f, m8 = -1e30f, l0s = 0.0f, l8s = 0.0f;

    const float* kvbase = kv + (size_t)(b * SEQ) * KV_DIM + h * (2 * HEAD_DIM);
    const float* mrow0  = mask + (size_t)(q0 + warp * 16 + (lane >> 2)) * SEQ
                               + ((lane & 3) << 1);

    const int srcA = (lane & 28) | ((lane & 3) >> 1);
    const int srcB = srcA | 2;
    const bool oddl = (lane & 1);

    for (int kt = 0; kt < SEQ / 64; kt++) {
        const int k0 = kt * 64;
        // ---- stage K tile ----
        const float* kb = kvbase + (size_t)k0 * KV_DIM;
        #pragma unroll
        for (int i = 0; i < 4; i++) {
            int idx = tid + i * 256;
            int kr  = idx >> 4;
            int c0  = (idx & 15) << 2;
            float4 v = *(const float4*)(kb + (size_t)kr * KV_DIM + c0);
            int kk   = c0 >> 3;
            int nt   = kr >> 3;
            int np   = nt >> 1;
            int slot = ((nt & 1) << 1) | ((c0 >> 2) & 1);
            int l0   = (kr & 7) << 2;
            int base = ((kk * 4 + np) * 32) * 4 + slot;
            Ks[base + (((l0 + 0) ^ kk) << 2)] = f2tff(v.x);
            Ks[base + (((l0 + 1) ^ kk) << 2)] = f2tff(v.y);
            Ks[base + (((l0 + 2) ^ kk) << 2)] = f2tff(v.z);
            Ks[base + (((l0 + 3) ^ kk) << 2)] = f2tff(v.w);
        }
        // ---- stage V tile ----
        const float* vb = kb + HEAD_DIM;
        #pragma unroll
        for (int i = 0; i < 4; i++) {
            int idx = tid + i * 256;
            int kr  = idx >> 4;
            int c0  = (idx & 15) << 2;
            float4 v = *(const float4*)(vb + (size_t)kr * KV_DIM + c0);
            int kk   = kr >> 3;
            int np   = c0 >> 4;
            int slot = (((c0 >> 3) & 1) << 1) | (((kr & 7) >= 4) ? 1 : 0);
            int l0   = ((c0 & 7) << 2) + (kr & 3);
            int base = ((kk * 4 + np) * 32) * 4 + slot;
            Vs[base + (((l0 +  0) ^ kk) << 2)] = f2tff(v.x);
            Vs[base + (((l0 +  4) ^ kk) << 2)] = f2tff(v.y);
            Vs[base + (((l0 +  8) ^ kk) << 2)] = f2tff(v.z);
            Vs[base + (((l0 + 12) ^ kk) << 2)] = f2tff(v.w);
        }
        __syncthreads();

        // ---- S = Q K^T ----
        float sf[8][4];
        #pragma unroll
        for (int nt = 0; nt < 8; nt++)
            #pragma unroll
            for (int r = 0; r < 4; r++) sf[nt][r] = 0.0f;

        #pragma unroll
        for (int kk = 0; kk < 8; kk++) {
            float4 aq = *(const float4*)&Qs[((warp * 8 + kk) * 32 + (lane ^ kk)) * 4];
            unsigned a0 = __float_as_uint(aq.x), a1 = __float_as_uint(aq.y);
            unsigned a2 = __float_as_uint(aq.z), a3 = __float_as_uint(aq.w);
            #pragma unroll
            for (int np = 0; np < 4; np++) {
                float4 kf = *(const float4*)&Ks[((kk * 4 + np) * 32 + (lane ^ kk)) * 4];
                mma_tf32(sf[2 * np],     a0, a1, a2, a3,
                         __float_as_uint(kf.x), __float_as_uint(kf.y));
                mma_tf32(sf[2 * np + 1], a0, a1, a2, a3,
                         __float_as_uint(kf.z), __float_as_uint(kf.w));
            }
        }

        // ---- mask add ----
        #pragma unroll
        for (int nt = 0; nt < 8; nt++) {
            float2 mv0 = *(const float2*)(mrow0 + k0 + nt * 8);
            float2 mv8 = *(const float2*)(mrow0 + (size_t)8 * SEQ + k0 + nt * 8);
            sf[nt][0] += mv0.x; sf[nt][1] += mv0.y;
            sf[nt][2] += mv8.x; sf[nt][3] += mv8.y;
        }

        // ---- online softmax ----
        float mx0 = -1e30f, mx8 = -1e30f;
        #pragma unroll
        for (int nt = 0; nt < 8; nt++) {
            mx0 = fmaxf(mx0, fmaxf(sf[nt][0], sf[nt][1]));
            mx8 = fmaxf(mx8, fmaxf(sf[nt][2], sf[nt][3]));
        }
        mx0 = fmaxf(mx0, __shfl_xor_sync(0xffffffffu, mx0, 1));
        mx0 = fmaxf(mx0, __shfl_xor_sync(0xffffffffu, mx0, 2));
        mx8 = fmaxf(mx8, __shfl_xor_sync(0xffffffffu, mx8, 1));
        mx8 = fmaxf(mx8, __shfl_xor_sync(0xffffffffu, mx8, 2));

        float nm0 = fmaxf(m0, mx0), nm8 = fmaxf(m8, mx8);
        float sc0 = __expf(m0 - nm0), sc8 = __expf(m8 - nm8);
        m0 = nm0; m8 = nm8;

        float rs0 = 0.0f, rs8 = 0.0f;
        #pragma unroll
        for (int nt = 0; nt < 8; nt++) {
            sf[nt][0] = __expf(sf[nt][0] - nm0); rs0 += sf[nt][0];
            sf[nt][1] = __expf(sf[nt][1] - nm0); rs0 += sf[nt][1];
            sf[nt][2] = __expf(sf[nt][2] - nm8); rs8 += sf[nt][2];
            sf[nt][3] = __expf(sf[nt][3] - nm8); rs8 += sf[nt][3];
        }
        rs0 += __shfl_xor_sync(0xffffffffu, rs0, 1);
        rs0 += __shfl_xor_sync(0xffffffffu, rs0, 2);
        rs8 += __shfl_xor_sync(0xffffffffu, rs8, 1);
        rs8 += __shfl_xor_sync(0xffffffffu, rs8, 2);
        l0s = l0s * sc0 + rs0;
        l8s = l8s * sc8 + rs8;

        #pragma unroll
        for (int nt = 0; nt < 8; nt++) {
            of[nt][0] *= sc0; of[nt][1] *= sc0;
            of[nt][2] *= sc8; of[nt][3] *= sc8;
        }

        // ---- O += P V (C-frag -> A-frag via shuffles) ----
        #pragma unroll
        for (int kk = 0; kk < 8; kk++) {
            float p0 = sf[kk][0], p1 = sf[kk][1], p2 = sf[kk][2], p3 = sf[kk][3];
            float e0 = __shfl_sync(0xffffffffu, p0, srcA);
            float e1 = __shfl_sync(0xffffffffu, p1, srcA);
            float e2 = __shfl_sync(0xffffffffu, p2, srcA);
            float e3 = __shfl_sync(0xffffffffu, p3, srcA);
            float g0 = __shfl_sync(0xffffffffu, p0, srcB);
            float g1 = __shfl_sync(0xffffffffu, p1, srcB);
            float g2 = __shfl_sync(0xffffffffu, p2, srcB);
            float g3 = __shfl_sync(0xffffffffu, p3, srcB);
            unsigned a0 = f2tf(oddl ? e1 : e0);
            unsigned a1 = f2tf(oddl ? e3 : e2);
            unsigned a2 = f2tf(oddl ? g1 : g0);
            unsigned a3 = f2tf(oddl ? g3 : g2);
            #pragma unroll
            for (int np = 0; np < 4; np++) {
                float4 vf = *(const float4*)&Vs[((kk * 4 + np) * 32 + (lane ^ kk)) * 4];
                mma_tf32(of[2 * np],     a0, a1, a2, a3,
                         __float_as_uint(vf.x), __float_as_uint(vf.y));
                mma_tf32(of[2 * np + 1], a0, a1, a2, a3,
                         __float_as_uint(vf.z), __float_as_uint(vf.w));
            }
        }
        __syncthreads();
    }

    // ---- normalize + store ----
    float inv0 = 1.0f / l0s, inv8 = 1.0f / l8s;
    float* obase = outp + (size_t)(b * SEQ + q0 + warp * 16 + (lane >> 2)) * D_MODEL
                        + h * HEAD_DIM + ((lane & 3) << 1);
    #pragma unroll
    for (int nt = 0; nt < 8; nt++) {
        float2 r0 = make_float2(of[nt][0] * inv0, of[nt][1] * inv0);
        float2 r8 = make_float2(of[nt][2] * inv8, of[nt][3] * inv8);
        *(float2*)(obase + nt * 8)                       = r0;
        *(float2*)(obase + (size_t)8 * D_MODEL + nt * 8) = r8;
    }
}

// ---------------------------------------------------------------------------
extern "C" void kernel_launch(void* const* d_in, const int* in_sizes, int n_in,
                              void* d_out, int out_size)
{
    const float* x    = (const float*)d_in[0];
    const float* y    = (const float*)d_in[1];
    const float* mask = (const float*)d_in[2];
    const float* Wq   = (const float*)d_in[3];
    const float* bq   = (const float*)d_in[4];
    const float* Wkv  = (const float*)d_in[5];
    const float* bkv  = (const float*)d_in[6];
    const float* Wo   = (const float*)d_in[7];
    const float* bo   = (const float*)d_in[8];
    float* out = (float*)d_out;

    float *qp, *kvp, *attnp;
    cudaGetSymbolAddress((void**)&qp,    g_q);
    cudaGetSymbolAddress((void**)&kvp,   g_kv);
    cudaGetSymbolAddress((void**)&attnp, g_attn);

    cudaFuncSetAttribute(gemm_proj_qkv,
                         cudaFuncAttributeMaxDynamicSharedMemorySize,
                         GEMM_SMEM_BYTES);
    cudaFuncSetAttribute(gemm_single,
                         cudaFuncAttributeMaxDynamicSharedMemorySize,
                         GEMM_SMEM_BYTES);
    cudaFuncSetAttribute(attn_tc_kernel,
                         cudaFuncAttributeMaxDynamicSharedMemorySize,
                         ATT_SMEM_BYTES);

    dim3 blk(256);

    // Q and KV projections, merged
    gemm_proj_qkv<<<dim3(18, M_TOT / 128), blk, GEMM_SMEM_BYTES>>>(
        x, y, Wq, bq, Wkv, bkv, qp, kvp);
    // attention
    attn_tc_kernel<<<dim3(SEQ / 128, NUM_HEADS, BATCH), blk, ATT_SMEM_BYTES>>>(
        qp, kvp, mask, attnp);
    // out = attn @ Wo^T + bo
    gemm_single<<<dim3(D_MODEL / 128, M_TOT / 128), blk, GEMM_SMEM_BYTES>>>(
        attnp, Wo, bo, out, D_MODEL, D_MODEL);
}

// round 7
// speedup vs baseline: 1.1581x; 1.0129x over previous
#include <cuda_runtime.h>
#include <cstdint>

#define D_MODEL   768
#define KV_DIM    1536
#define NUM_HEADS 12
#define HEAD_DIM  64
#define BATCH     4
#define SEQ       2048
#define M_TOT     (BATCH * SEQ)   // 8192

// Scratch (no allocations allowed anywhere)
__device__ float g_q[M_TOT * D_MODEL];
__device__ float g_kv[M_TOT * KV_DIM];
__device__ float g_attn[M_TOT * D_MODEL];

// ---------------------------------------------------------------------------
// helpers
// ---------------------------------------------------------------------------
__device__ __forceinline__ unsigned f2tf(float f) {
    unsigned r;
    asm("cvt.rna.tf32.f32 %0, %1;" : "=r"(r) : "f"(f));
    return r;
}
__device__ __forceinline__ float f2tff(float f) {
    return __uint_as_float(f2tf(f));
}
__device__ __forceinline__ unsigned u2tf(unsigned u) {
    unsigned r;
    asm("cvt.rna.tf32.f32 %0, %1;" : "=r"(r) : "f"(__uint_as_float(u)));
    return r;
}

__device__ __forceinline__ void mma_tf32(float c[4],
                                         unsigned a0, unsigned a1,
                                         unsigned a2, unsigned a3,
                                         unsigned b0, unsigned b1)
{
    asm("mma.sync.aligned.m16n8k8.row.col.f32.tf32.tf32.f32 "
        "{%0,%1,%2,%3}, {%4,%5,%6,%7}, {%8,%9}, {%0,%1,%2,%3};\n"
        : "+f"(c[0]), "+f"(c[1]), "+f"(c[2]), "+f"(c[3])
        : "r"(a0), "r"(a1), "r"(a2), "r"(a3), "r"(b0), "r"(b1));
}

__device__ __forceinline__ void cp16(unsigned saddr, const void* gptr) {
    asm volatile("cp.async.cg.shared.global [%0], [%1], 16;\n"
                 :: "r"(saddr), "l"(gptr));
}
__device__ __forceinline__ void cp_commit() {
    asm volatile("cp.async.commit_group;\n" ::: "memory");
}

__device__ __forceinline__ void ldsm_x4(unsigned& d0, unsigned& d1,
                                        unsigned& d2, unsigned& d3,
                                        unsigned saddr)
{
    asm volatile("ldmatrix.sync.aligned.m8n8.x4.shared.b16 {%0,%1,%2,%3}, [%4];\n"
                 : "=r"(d0), "=r"(d1), "=r"(d2), "=r"(d3) : "r"(saddr));
}

// ---------------------------------------------------------------------------
// Pipelined tf32 GEMM: C = A @ W^T + bias over one 128x128 tile.
// cp.async (swizzled raw fp32) TRIPLE-buffer -> ldmatrix -> cvt.tf32 -> mma.
// Raw tile: 128 rows x 32 floats; swizzle chunk' = chunk ^ (row & 7).
// smem: rawA[3][4096] + rawB[3][4096] floats = 96 KB.
// ---------------------------------------------------------------------------
#define GEMM_SMEM_BYTES (24576 * 4)

__device__ __forceinline__ void gemm_pipe(const float* __restrict__ Ab,
                                          const float* __restrict__ Wb,
                                          const float* __restrict__ biasp,
                                          float* __restrict__ Cb,
                                          int N, int K, float* sm)
{
    float* rawA = sm;             // [3][4096]
    float* rawB = sm + 12288;     // [3][4096]

    const int tid  = threadIdx.x;
    const int lane = tid & 31;
    const int warp = tid >> 5;
    const int wm   = warp & 1;
    const int wn   = warp >> 1;

    const unsigned rawA_s = (unsigned)__cvta_generic_to_shared(rawA);
    const unsigned rawB_s = (unsigned)__cvta_generic_to_shared(rawB);

    const int srow = tid >> 3;          // 0..31
    const int sch  = tid & 7;           // 16B chunk within row

    float acc[4][4][4];
    #pragma unroll
    for (int i = 0; i < 4; i++)
        #pragma unroll
        for (int j = 0; j < 4; j++)
            #pragma unroll
            for (int r = 0; r < 4; r++) acc[i][j][r] = 0.0f;

    const int ntile = K >> 5;

    const int a_row = wm * 64 + (lane & 15);
    const int a_chv = (lane >> 4);
    const int b_row = wn * 32 + ((lane >> 4) << 3) + (lane & 7);
    const int b_chv = (lane >> 3) & 1;

    // prologue: stage tiles 0 and 1
    #pragma unroll
    for (int i = 0; i < 4; i++) {
        int row = srow + i * 32;
        int sw  = sch ^ (row & 7);
        cp16(rawA_s + (row * 32 + sw * 4) * 4, Ab + (size_t)row * K + sch * 4);
        cp16(rawB_s + (row * 32 + sw * 4) * 4, Wb + (size_t)row * K + sch * 4);
    }
    cp_commit();
    if (1 < ntile) {
        #pragma unroll
        for (int i = 0; i < 4; i++) {
            int row = srow + i * 32;
            int sw  = sch ^ (row & 7);
            cp16(rawA_s + (4096 + row * 32 + sw * 4) * 4,
                 Ab + (size_t)row * K + 32 + sch * 4);
            cp16(rawB_s + (4096 + row * 32 + sw * 4) * 4,
                 Wb + (size_t)row * K + 32 + sch * 4);
        }
    }
    cp_commit();

    int st = 0;
    for (int t = 0; t < ntile; t++) {
        if (t + 2 < ntile) {
            const int koff = (t + 2) << 5;
            int ns = st + 2; if (ns >= 3) ns -= 3;
            #pragma unroll
            for (int i = 0; i < 4; i++) {
                int row = srow + i * 32;
                int sw  = sch ^ (row & 7);
                cp16(rawA_s + (ns * 4096 + row * 32 + sw * 4) * 4,
                     Ab + (size_t)row * K + koff + sch * 4);
                cp16(rawB_s + (ns * 4096 + row * 32 + sw * 4) * 4,
                     Wb + (size_t)row * K + koff + sch * 4);
            }
            cp_commit();
            asm volatile("cp.async.wait_group 2;\n" ::: "memory");
        } else if (t + 1 < ntile) {
            asm volatile("cp.async.wait_group 1;\n" ::: "memory");
        } else {
            asm volatile("cp.async.wait_group 0;\n" ::: "memory");
        }
        __syncthreads();

        const unsigned baseA = rawA_s + st * 16384;
        const unsigned baseB = rawB_s + st * 16384;

        #pragma unroll
        for (int kk = 0; kk < 4; kk++) {
            unsigned a[4][4], b[4][2];
            #pragma unroll
            for (int mt = 0; mt < 4; mt++) {
                int row = a_row + mt * 16;
                int ch  = kk * 2 + a_chv;
                unsigned ad = baseA + row * 128 + ((ch ^ (row & 7)) << 4);
                ldsm_x4(a[mt][0], a[mt][1], a[mt][2], a[mt][3], ad);
            }
            #pragma unroll
            for (int p = 0; p < 2; p++) {
                int row = b_row + p * 16;
                int ch  = kk * 2 + b_chv;
                unsigned bd = baseB + row * 128 + ((ch ^ (row & 7)) << 4);
                ldsm_x4(b[2 * p][0], b[2 * p][1], b[2 * p + 1][0], b[2 * p + 1][1], bd);
            }
            #pragma unroll
            for (int mt = 0; mt < 4; mt++)
                #pragma unroll
                for (int r = 0; r < 4; r++) a[mt][r] = u2tf(a[mt][r]);
            #pragma unroll
            for (int nt = 0; nt < 4; nt++) {
                b[nt][0] = u2tf(b[nt][0]);
                b[nt][1] = u2tf(b[nt][1]);
            }
            #pragma unroll
            for (int mt = 0; mt < 4; mt++)
                #pragma unroll
                for (int nt = 0; nt < 4; nt++)
                    mma_tf32(acc[mt][nt], a[mt][0], a[mt][1], a[mt][2], a[mt][3],
                             b[nt][0], b[nt][1]);
        }
        __syncthreads();
        st++; if (st == 3) st = 0;
    }

    // ---- epilogue: bias + store ----
    #pragma unroll
    for (int mt = 0; mt < 4; mt++) {
        int row = (wm * 4 + mt) * 16 + (lane >> 2);
        #pragma unroll
        for (int nt = 0; nt < 4; nt++) {
            int col = (wn * 4 + nt) * 8 + ((lane & 3) << 1);
            float2 bv = *(const float2*)(biasp + col);
            float2 r0, r1;
            r0.x = acc[mt][nt][0] + bv.x;
            r0.y = acc[mt][nt][1] + bv.y;
            r1.x = acc[mt][nt][2] + bv.x;
            r1.y = acc[mt][nt][3] + bv.y;
            *(float2*)(Cb + (size_t)row * N + col)       = r0;
            *(float2*)(Cb + (size_t)(row + 8) * N + col) = r1;
        }
    }
}

// Merged Q + KV projection: grid (18, 64). x<6 -> Q column block, else KV.
__global__ __launch_bounds__(256, 2)
void gemm_proj_qkv(const float* __restrict__ x, const float* __restrict__ y,
                   const float* __restrict__ Wq, const float* __restrict__ bq,
                   const float* __restrict__ Wkv, const float* __restrict__ bkv,
                   float* __restrict__ qout, float* __restrict__ kvout)
{
    extern __shared__ float dsm[];
    const int bx = blockIdx.x, by = blockIdx.y;
    if (bx < 6) {
        gemm_pipe(x + (size_t)by * 128 * D_MODEL,
                  Wq + (size_t)bx * 128 * D_MODEL,
                  bq + bx * 128,
                  qout + (size_t)by * 128 * D_MODEL + bx * 128,
                  D_MODEL, D_MODEL, dsm);
    } else {
        const int cx = bx - 6;
        gemm_pipe(y + (size_t)by * 128 * D_MODEL,
                  Wkv + (size_t)cx * 128 * D_MODEL,
                  bkv + cx * 128,
                  kvout + (size_t)by * 128 * KV_DIM + cx * 128,
                  KV_DIM, D_MODEL, dsm);
    }
}

__global__ __launch_bounds__(256, 2)
void gemm_single(const float* __restrict__ A, const float* __restrict__ W,
                 const float* __restrict__ bias, float* __restrict__ C,
                 int N, int K)
{
    extern __shared__ float dsm[];
    gemm_pipe(A + (size_t)blockIdx.y * 128 * K,
              W + (size_t)blockIdx.x * 128 * K,
              bias + blockIdx.x * 128,
              C + (size_t)blockIdx.y * 128 * N + blockIdx.x * 128,
              N, K, dsm);
}

// ---------------------------------------------------------------------------
// Tensor-core flash attention, cp.async double-buffered K/V raw staging.
// Grid: (S/128, H, B). Block: 256 threads = 8 warps.
//
// smem (floats):
//   Qs  [0, 8192)        A-fragment permuted Q (tf32, pre-scaled)
//   raw [8192, 24576)    2 stages x 64 rows x 128 floats (16B-chunk swizzled)
//   Vf  [24576, 28672)   single-stage B-fragment permuted V (tf32)
// K fragments are read directly from raw via ldmatrix (row stride 512 B,
// chunk swizzle ch^(row&7)), then cvt.rna.tf32 in registers.
// Total 114,688 B -> 2 CTAs/SM.
// ---------------------------------------------------------------------------
#define ATT_SMEM_BYTES (28672 * 4)

__global__ __launch_bounds__(256, 2)
void attn_tc_kernel(const float* __restrict__ q, const float* __restrict__ kv,
                    const float* __restrict__ mask, float* __restrict__ outp)
{
    extern __shared__ float sm[];
    float* Qs   = sm;
    float* rawp = sm + 8192;
    float* Vf   = sm + 24576;

    const int tid  = threadIdx.x;
    const int lane = tid & 31;
    const int warp = tid >> 5;
    const int qt = blockIdx.x, h = blockIdx.y, b = blockIdx.z;
    const int q0 = qt * 128;

    const unsigned raw_s = (unsigned)__cvta_generic_to_shared(rawp);

    // ---- stage Q (scaled, tf32, A-fragment permuted) ----
    {
        const float* qbase = q + (size_t)(b * SEQ + q0) * D_MODEL + h * HEAD_DIM;
        #pragma unroll
        for (int i = 0; i < 8; i++) {
            int idx = tid + i * 256;
            int row = idx >> 4;
            int c0  = (idx & 15) << 2;
            float4 v = *(const float4*)(qbase + (size_t)row * D_MODEL + c0);
            int w  = row >> 4;
            int r  = row & 15;
            int kk = c0 >> 3;
            int j  = ((r >> 3) & 1) | ((c0 & 4) ? 2 : 0);
            int l0 = (r & 7) << 2;
            int base = ((w * 8 + kk) * 32) * 4 + j;
            Qs[base + (((l0 + 0) ^ kk) << 2)] = f2tff(v.x * 0.125f);
            Qs[base + (((l0 + 1) ^ kk) << 2)] = f2tff(v.y * 0.125f);
            Qs[base + (((l0 + 2) ^ kk) << 2)] = f2tff(v.z * 0.125f);
            Qs[base + (((l0 + 3) ^ kk) << 2)] = f2tff(v.w * 0.125f);
        }
    }

    float of[8][4];
    #pragma unroll
    for (int nt = 0; nt < 8; nt++)
        #pragma unroll
        for (int r = 0; r < 4; r++) of[nt][r] = 0.0f;
    float m0 = -1e30f, m8 = -1e30f, l0s = 0.0f, l8s = 0.0f;

    const float* kvbase = kv + (size_t)(b * SEQ) * KV_DIM + h * (2 * HEAD_DIM);
    const float* mrow0  = mask + (size_t)(q0 + warp * 16 + (lane >> 2)) * SEQ
                               + ((lane & 3) << 1);

    const int srcA = (lane & 28) | ((lane & 3) >> 1);
    const int srcB = srcA | 2;
    const bool oddl = (lane & 1);

    // cp.async staging coords: 8 chunks/thread; warp w stages rows w + i*8.
    const int crow = tid >> 5;
    const int cch  = tid & 31;

    // K ldmatrix coords
    const int k_rowb = ((lane >> 4) << 3) + (lane & 7);
    const int k_chv  = (lane >> 3) & 1;

    // prologue: stage tile 0 into raw stage 0
    #pragma unroll
    for (int i = 0; i < 8; i++) {
        int row = crow + i * 8;
        int sw  = cch ^ (row & 7);
        cp16(raw_s + (row * 128 + sw * 4) * 4,
             kvbase + (size_t)row * KV_DIM + cch * 4);
    }
    cp_commit();

    for (int kt = 0; kt < SEQ / 64; kt++) {
        const int k0 = kt * 64;
        const int s  = kt & 1;

        if (kt + 1 < SEQ / 64) {
            const float* kbn = kvbase + (size_t)(k0 + 64) * KV_DIM;
            const unsigned dst = raw_s + (s ^ 1) * 32768;
            #pragma unroll
            for (int i = 0; i < 8; i++) {
                int row = crow + i * 8;
                int sw  = cch ^ (row & 7);
                cp16(dst + (row * 128 + sw * 4) * 4,
                     kbn + (size_t)row * KV_DIM + cch * 4);
            }
            cp_commit();
            asm volatile("cp.async.wait_group 1;\n" ::: "memory");
        } else {
            asm volatile("cp.async.wait_group 0;\n" ::: "memory");
        }
        __syncthreads();   // tile-t raw data visible to all warps

        // ---- permute raw[s] V half -> Vf (single stage) ----
        const float* rp = rawp + s * 8192;
        #pragma unroll
        for (int i = 0; i < 4; i++) {
            int idx = tid + i * 256;
            int kr  = idx >> 4;
            int c0  = (idx & 15) << 2;
            float4 w = *(const float4*)&rp[kr * 128
                          + (((16 + (c0 >> 2)) ^ (kr & 7)) << 2)];
            int kk   = kr >> 3;
            int np   = c0 >> 4;
            int slot = (((c0 >> 3) & 1) << 1) | (((kr & 7) >= 4) ? 1 : 0);
            int l0   = ((c0 & 7) << 2) + (kr & 3);
            int base = ((kk * 4 + np) * 32) * 4 + slot;
            Vf[base + (((l0 +  0) ^ kk) << 2)] = f2tff(w.x);
            Vf[base + (((l0 +  4) ^ kk) << 2)] = f2tff(w.y);
            Vf[base + (((l0 +  8) ^ kk) << 2)] = f2tff(w.z);
            Vf[base + (((l0 + 12) ^ kk) << 2)] = f2tff(w.w);
        }
        __syncthreads();   // Vf visible

        // ---- S = Q K^T (K fragments via ldmatrix from raw) ----
        const unsigned kbase = raw_s + s * 32768;
        float sf[8][4];
        #pragma unroll
        for (int nt = 0; nt < 8; nt++)
            #pragma unroll
            for (int r = 0; r < 4; r++) sf[nt][r] = 0.0f;

        #pragma unroll
        for (int kk = 0; kk < 8; kk++) {
            float4 aq = *(const float4*)&Qs[((warp * 8 + kk) * 32 + (lane ^ kk)) * 4];
            unsigned a0 = __float_as_uint(aq.x), a1 = __float_as_uint(aq.y);
            unsigned a2 = __float_as_uint(aq.z), a3 = __float_as_uint(aq.w);
            const int ch = kk * 2 + k_chv;
            #pragma unroll
            for (int np = 0; np < 4; np++) {
                int row = np * 16 + k_rowb;
                unsigned kd = kbase + row * 512 + ((ch ^ (row & 7)) << 4);
                unsigned d0, d1, d2, d3;
                ldsm_x4(d0, d1, d2, d3, kd);
                mma_tf32(sf[2 * np],     a0, a1, a2, a3, u2tf(d0), u2tf(d1));
                mma_tf32(sf[2 * np + 1], a0, a1, a2, a3, u2tf(d2), u2tf(d3));
            }
        }

        // ---- mask add ----
        #pragma unroll
        for (int nt = 0; nt < 8; nt++) {
            float2 mv0 = *(const float2*)(mrow0 + k0 + nt * 8);
            float2 mv8 = *(const float2*)(mrow0 + (size_t)8 * SEQ + k0 + nt * 8);
            sf[nt][0] += mv0.x; sf[nt][1] += mv0.y;
            sf[nt][2] += mv8.x; sf[nt][3] += mv8.y;
        }

        // ---- online softmax ----
        float mx0 = -1e30f, mx8 = -1e30f;
        #pragma unroll
        for (int nt = 0; nt < 8; nt++) {
            mx0 = fmaxf(mx0, fmaxf(sf[nt][0], sf[nt][1]));
            mx8 = fmaxf(mx8, fmaxf(sf[nt][2], sf[nt][3]));
        }
        mx0 = fmaxf(mx0, __shfl_xor_sync(0xffffffffu, mx0, 1));
        mx0 = fmaxf(mx0, __shfl_xor_sync(0xffffffffu, mx0, 2));
        mx8 = fmaxf(mx8, __shfl_xor_sync(0xffffffffu, mx8, 1));
        mx8 = fmaxf(mx8, __shfl_xor_sync(0xffffffffu, mx8, 2));

        float nm0 = fmaxf(m0, mx0), nm8 = fmaxf(m8, mx8);
        float sc0 = __expf(m0 - nm0), sc8 = __expf(m8 - nm8);
        m0 = nm0; m8 = nm8;

        float rs0 = 0.0f, rs8 = 0.0f;
        #pragma unroll
        for (int nt = 0; nt < 8; nt++) {
            sf[nt][0] = __expf(sf[nt][0] - nm0); rs0 += sf[nt][0];
            sf[nt][1] = __expf(sf[nt][1] - nm0); rs0 += sf[nt][1];
            sf[nt][2] = __expf(sf[nt][2] - nm8); rs8 += sf[nt][2];
            sf[nt][3] = __expf(sf[nt][3] - nm8); rs8 += sf[nt][3];
        }
        rs0 += __shfl_xor_sync(0xffffffffu, rs0, 1);
        rs0 += __shfl_xor_sync(0xffffffffu, rs0, 2);
        rs8 += __shfl_xor_sync(0xffffffffu, rs8, 1);
        rs8 += __shfl_xor_sync(0xffffffffu, rs8, 2);
        l0s = l0s * sc0 + rs0;
        l8s = l8s * sc8 + rs8;

        #pragma unroll
        for (int nt = 0; nt < 8; nt++) {
            of[nt][0] *= sc0; of[nt][1] *= sc0;
            of[nt][2] *= sc8; of[nt][3] *= sc8;
        }

        // ---- O += P V (C-frag -> A-frag via shuffles) ----
        #pragma unroll
        for (int kk = 0; kk < 8; kk++) {
            float p0 = sf[kk][0], p1 = sf[kk][1], p2 = sf[kk][2], p3 = sf[kk][3];
            float e0 = __shfl_sync(0xffffffffu, p0, srcA);
            float e1 = __shfl_sync(0xffffffffu, p1, srcA);
            float e2 = __shfl_sync(0xffffffffu, p2, srcA);
            float e3 = __shfl_sync(0xffffffffu, p3, srcA);
            float g0 = __shfl_sync(0xffffffffu, p0, srcB);
            float g1 = __shfl_sync(0xffffffffu, p1, srcB);
            float g2 = __shfl_sync(0xffffffffu, p2, srcB);
            float g3 = __shfl_sync(0xffffffffu, p3, srcB);
            unsigned a0 = f2tf(oddl ? e1 : e0);
            unsigned a1 = f2tf(oddl ? e3 : e2);
            unsigned a2 = f2tf(oddl ? g1 : g0);
            unsigned a3 = f2tf(oddl ? g3 : g2);
            #pragma unroll
            for (int np = 0; np < 4; np++) {
                float4 vf = *(const float4*)&Vf[((kk * 4 + np) * 32 + (lane ^ kk)) * 4];
                mma_tf32(of[2 * np],     a0, a1, a2, a3,
                         __float_as_uint(vf.x), __float_as_uint(vf.y));
                mma_tf32(of[2 * np + 1], a0, a1, a2, a3,
                         __float_as_uint(vf.z), __float_as_uint(vf.w));
            }
        }
        __syncthreads();   // protect raw[s] + Vf before next iteration writes
    }

    // ---- normalize + store ----
    float inv0 = 1.0f / l0s, inv8 = 1.0f / l8s;
    float* obase = outp + (size_t)(b * SEQ + q0 + warp * 16 + (lane >> 2)) * D_MODEL
                        + h * HEAD_DIM + ((lane & 3) << 1);
    #pragma unroll
    for (int nt = 0; nt < 8; nt++) {
        float2 r0 = make_float2(of[nt][0] * inv0, of[nt][1] * inv0);
        float2 r8 = make_float2(of[nt][2] * inv8, of[nt][3] * inv8);
        *(float2*)(obase + nt * 8)                       = r0;
        *(float2*)(obase + (size_t)8 * D_MODEL + nt * 8) = r8;
    }
}

// ---------------------------------------------------------------------------
extern "C" void kernel_launch(void* const* d_in, const int* in_sizes, int n_in,
                              void* d_out, int out_size)
{
    const float* x    = (const float*)d_in[0];
    const float* y    = (const float*)d_in[1];
    const float* mask = (const float*)d_in[2];
    const float* Wq   = (const float*)d_in[3];
    const float* bq   = (const float*)d_in[4];
    const float* Wkv  = (const float*)d_in[5];
    const float* bkv  = (const float*)d_in[6];
    const float* Wo   = (const float*)d_in[7];
    const float* bo   = (const float*)d_in[8];
    float* out = (float*)d_out;

    float *qp, *kvp, *attnp;
    cudaGetSymbolAddress((void**)&qp,    g_q);
    cudaGetSymbolAddress((void**)&kvp,   g_kv);
    cudaGetSymbolAddress((void**)&attnp, g_attn);

    cudaFuncSetAttribute(gemm_proj_qkv,
                         cudaFuncAttributeMaxDynamicSharedMemorySize,
                         GEMM_SMEM_BYTES);
    cudaFuncSetAttribute(gemm_single,
                         cudaFuncAttributeMaxDynamicSharedMemorySize,
                         GEMM_SMEM_BYTES);
    cudaFuncSetAttribute(attn_tc_kernel,
                         cudaFuncAttributeMaxDynamicSharedMemorySize,
                         ATT_SMEM_BYTES);

    dim3 blk(256);

    // Q and KV projections, merged
    gemm_proj_qkv<<<dim3(18, M_TOT / 128), blk, GEMM_SMEM_BYTES>>>(
        x, y, Wq, bq, Wkv, bkv, qp, kvp);
    // attention
    attn_tc_kernel<<<dim3(SEQ / 128, NUM_HEADS, BATCH), blk, ATT_SMEM_BYTES>>>(
        qp, kvp, mask, attnp);
    // out = attn @ Wo^T + bo
    gemm_single<<<dim3(D_MODEL / 128, M_TOT / 128), blk, GEMM_SMEM_BYTES>>>(
        attnp, Wo, bo, out, D_MODEL, D_MODEL);
}

// round 8
// speedup vs baseline: 1.1713x; 1.0114x over previous
#include <cuda_runtime.h>
#include <cstdint>

#define D_MODEL   768
#define KV_DIM    1536
#define NUM_HEADS 12
#define HEAD_DIM  64
#define BATCH     4
#define SEQ       2048
#define M_TOT     (BATCH * SEQ)   // 8192

#define N_X   (M_TOT * D_MODEL)
#define N_WQ  (D_MODEL * D_MODEL)
#define N_WKV (KV_DIM * D_MODEL)
#define N_WO  (D_MODEL * D_MODEL)

// Scratch (no allocations allowed anywhere)
__device__ float g_q[M_TOT * D_MODEL];     // tf32-rounded, pre-scaled Q
__device__ float g_kv[M_TOT * KV_DIM];     // tf32-rounded KV
__device__ float g_attn[M_TOT * D_MODEL];  // tf32-rounded attention out
__device__ float g_xr[N_X];                // tf32-rounded x
__device__ float g_yr[N_X];                // tf32-rounded y
__device__ float g_wq[N_WQ];               // tf32-rounded Wq
__device__ float g_wkv[N_WKV];             // tf32-rounded Wkv
__device__ float g_wo[N_WO];               // tf32-rounded Wo

// ---------------------------------------------------------------------------
// helpers
// ---------------------------------------------------------------------------
__device__ __forceinline__ unsigned f2tf(float f) {
    unsigned r;
    asm("cvt.rna.tf32.f32 %0, %1;" : "=r"(r) : "f"(f));
    return r;
}
__device__ __forceinline__ float f2tff(float f) {
    return __uint_as_float(f2tf(f));
}

__device__ __forceinline__ void mma_tf32(float c[4],
                                         unsigned a0, unsigned a1,
                                         unsigned a2, unsigned a3,
                                         unsigned b0, unsigned b1)
{
    asm("mma.sync.aligned.m16n8k8.row.col.f32.tf32.tf32.f32 "
        "{%0,%1,%2,%3}, {%4,%5,%6,%7}, {%8,%9}, {%0,%1,%2,%3};\n"
        : "+f"(c[0]), "+f"(c[1]), "+f"(c[2]), "+f"(c[3])
        : "r"(a0), "r"(a1), "r"(a2), "r"(a3), "r"(b0), "r"(b1));
}

__device__ __forceinline__ void cp16(unsigned saddr, const void* gptr) {
    asm volatile("cp.async.cg.shared.global [%0], [%1], 16;\n"
                 :: "r"(saddr), "l"(gptr));
}
__device__ __forceinline__ void cp_commit() {
    asm volatile("cp.async.commit_group;\n" ::: "memory");
}

__device__ __forceinline__ void ldsm_x4(unsigned& d0, unsigned& d1,
                                        unsigned& d2, unsigned& d3,
                                        unsigned saddr)
{
    asm volatile("ldmatrix.sync.aligned.m8n8.x4.shared.b16 {%0,%1,%2,%3}, [%4];\n"
                 : "=r"(d0), "=r"(d1), "=r"(d2), "=r"(d3) : "r"(saddr));
}

// ---------------------------------------------------------------------------
// Pre-round pass: tf32-round x, y, Wq, Wkv, Wo into scratch (float4 granular).
// ---------------------------------------------------------------------------
#define X4   (N_X / 4)
#define WQ4  (N_WQ / 4)
#define WKV4 (N_WKV / 4)
#define PREP_TOTAL4 (2 * X4 + 2 * WQ4 + WKV4)

__global__ void prep_round(const float* __restrict__ x, const float* __restrict__ y,
                           const float* __restrict__ Wq, const float* __restrict__ Wkv,
                           const float* __restrict__ Wo,
                           float* __restrict__ xr, float* __restrict__ yr,
                           float* __restrict__ wq, float* __restrict__ wkv,
                           float* __restrict__ wo)
{
    int i = blockIdx.x * blockDim.x + threadIdx.x;
    if (i >= PREP_TOTAL4) return;
    const float* src;
    float* dst;
    int off;
    if (i < X4)                         { src = x;   dst = xr;  off = i; }
    else if (i < 2 * X4)                { src = y;   dst = yr;  off = i - X4; }
    else if (i < 2 * X4 + WQ4)          { src = Wq;  dst = wq;  off = i - 2 * X4; }
    else if (i < 2 * X4 + WQ4 + WKV4)   { src = Wkv; dst = wkv; off = i - 2 * X4 - WQ4; }
    else                                { src = Wo;  dst = wo;  off = i - 2 * X4 - WQ4 - WKV4; }
    float4 v = *(const float4*)(src + (size_t)off * 4);
    v.x = f2tff(v.x); v.y = f2tff(v.y); v.z = f2tff(v.z); v.w = f2tff(v.w);
    *(float4*)(dst + (size_t)off * 4) = v;
}

// ---------------------------------------------------------------------------
// Pipelined tf32 GEMM: C = A @ W^T + bias over one 128x128 tile.
// Inputs pre-rounded to tf32 -> ldmatrix feeds mma directly (no cvt).
// Epilogue: out = (acc + bias) * oscale, optionally tf32-rounded.
// ---------------------------------------------------------------------------
#define GEMM_SMEM_BYTES (24576 * 4)

__device__ __forceinline__ void gemm_pipe(const float* __restrict__ Ab,
                                          const float* __restrict__ Wb,
                                          const float* __restrict__ biasp,
                                          float* __restrict__ Cb,
                                          int N, int K, float* sm,
                                          float oscale, int round_out)
{
    float* rawA = sm;             // [3][4096]
    float* rawB = sm + 12288;     // [3][4096]

    const int tid  = threadIdx.x;
    const int lane = tid & 31;
    const int warp = tid >> 5;
    const int wm   = warp & 1;
    const int wn   = warp >> 1;

    const unsigned rawA_s = (unsigned)__cvta_generic_to_shared(rawA);
    const unsigned rawB_s = (unsigned)__cvta_generic_to_shared(rawB);

    const int srow = tid >> 3;
    const int sch  = tid & 7;

    float acc[4][4][4];
    #pragma unroll
    for (int i = 0; i < 4; i++)
        #pragma unroll
        for (int j = 0; j < 4; j++)
            #pragma unroll
            for (int r = 0; r < 4; r++) acc[i][j][r] = 0.0f;

    const int ntile = K >> 5;

    const int a_row = wm * 64 + (lane & 15);
    const int a_chv = (lane >> 4);
    const int b_row = wn * 32 + ((lane >> 4) << 3) + (lane & 7);
    const int b_chv = (lane >> 3) & 1;

    #pragma unroll
    for (int i = 0; i < 4; i++) {
        int row = srow + i * 32;
        int sw  = sch ^ (row & 7);
        cp16(rawA_s + (row * 32 + sw * 4) * 4, Ab + (size_t)row * K + sch * 4);
        cp16(rawB_s + (row * 32 + sw * 4) * 4, Wb + (size_t)row * K + sch * 4);
    }
    cp_commit();
    if (1 < ntile) {
        #pragma unroll
        for (int i = 0; i < 4; i++) {
            int row = srow + i * 32;
            int sw  = sch ^ (row & 7);
            cp16(rawA_s + (4096 + row * 32 + sw * 4) * 4,
                 Ab + (size_t)row * K + 32 + sch * 4);
            cp16(rawB_s + (4096 + row * 32 + sw * 4) * 4,
                 Wb + (size_t)row * K + 32 + sch * 4);
        }
    }
    cp_commit();

    int st = 0;
    for (int t = 0; t < ntile; t++) {
        if (t + 2 < ntile) {
            const int koff = (t + 2) << 5;
            int ns = st + 2; if (ns >= 3) ns -= 3;
            #pragma unroll
            for (int i = 0; i < 4; i++) {
                int row = srow + i * 32;
                int sw  = sch ^ (row & 7);
                cp16(rawA_s + (ns * 4096 + row * 32 + sw * 4) * 4,
                     Ab + (size_t)row * K + koff + sch * 4);
                cp16(rawB_s + (ns * 4096 + row * 32 + sw * 4) * 4,
                     Wb + (size_t)row * K + koff + sch * 4);
            }
            cp_commit();
            asm volatile("cp.async.wait_group 2;\n" ::: "memory");
        } else if (t + 1 < ntile) {
            asm volatile("cp.async.wait_group 1;\n" ::: "memory");
        } else {
            asm volatile("cp.async.wait_group 0;\n" ::: "memory");
        }
        __syncthreads();

        const unsigned baseA = rawA_s + st * 16384;
        const unsigned baseB = rawB_s + st * 16384;

        #pragma unroll
        for (int kk = 0; kk < 4; kk++) {
            unsigned a[4][4], b[4][2];
            #pragma unroll
            for (int mt = 0; mt < 4; mt++) {
                int row = a_row + mt * 16;
                int ch  = kk * 2 + a_chv;
                unsigned ad = baseA + row * 128 + ((ch ^ (row & 7)) << 4);
                ldsm_x4(a[mt][0], a[mt][1], a[mt][2], a[mt][3], ad);
            }
            #pragma unroll
            for (int p = 0; p < 2; p++) {
                int row = b_row + p * 16;
                int ch  = kk * 2 + b_chv;
                unsigned bd = baseB + row * 128 + ((ch ^ (row & 7)) << 4);
                ldsm_x4(b[2 * p][0], b[2 * p][1], b[2 * p + 1][0], b[2 * p + 1][1], bd);
            }
            #pragma unroll
            for (int mt = 0; mt < 4; mt++)
                #pragma unroll
                for (int nt = 0; nt < 4; nt++)
                    mma_tf32(acc[mt][nt], a[mt][0], a[mt][1], a[mt][2], a[mt][3],
                             b[nt][0], b[nt][1]);
        }
        __syncthreads();
        st++; if (st == 3) st = 0;
    }

    // ---- epilogue: bias + scale (+ optional tf32 rounding) + store ----
    #pragma unroll
    for (int mt = 0; mt < 4; mt++) {
        int row = (wm * 4 + mt) * 16 + (lane >> 2);
        #pragma unroll
        for (int nt = 0; nt < 4; nt++) {
            int col = (wn * 4 + nt) * 8 + ((lane & 3) << 1);
            float2 bv = *(const float2*)(biasp + col);
            float2 r0, r1;
            r0.x = (acc[mt][nt][0] + bv.x) * oscale;
            r0.y = (acc[mt][nt][1] + bv.y) * oscale;
            r1.x = (acc[mt][nt][2] + bv.x) * oscale;
            r1.y = (acc[mt][nt][3] + bv.y) * oscale;
            if (round_out) {
                r0.x = f2tff(r0.x); r0.y = f2tff(r0.y);
                r1.x = f2tff(r1.x); r1.y = f2tff(r1.y);
            }
            *(float2*)(Cb + (size_t)row * N + col)       = r0;
            *(float2*)(Cb + (size_t)(row + 8) * N + col) = r1;
        }
    }
}

// Merged Q + KV projection: grid (18, 64). x<6 -> Q column block, else KV.
__global__ __launch_bounds__(256, 2)
void gemm_proj_qkv(const float* __restrict__ x, const float* __restrict__ y,
                   const float* __restrict__ Wq, const float* __restrict__ bq,
                   const float* __restrict__ Wkv, const float* __restrict__ bkv,
                   float* __restrict__ qout, float* __restrict__ kvout)
{
    extern __shared__ float dsm[];
    const int bx = blockIdx.x, by = blockIdx.y;
    if (bx < 6) {
        gemm_pipe(x + (size_t)by * 128 * D_MODEL,
                  Wq + (size_t)bx * 128 * D_MODEL,
                  bq + bx * 128,
                  qout + (size_t)by * 128 * D_MODEL + bx * 128,
                  D_MODEL, D_MODEL, dsm, 0.125f, 1);
    } else {
        const int cx = bx - 6;
        gemm_pipe(y + (size_t)by * 128 * D_MODEL,
                  Wkv + (size_t)cx * 128 * D_MODEL,
                  bkv + cx * 128,
                  kvout + (size_t)by * 128 * KV_DIM + cx * 128,
                  KV_DIM, D_MODEL, dsm, 1.0f, 1);
    }
}

__global__ __launch_bounds__(256, 2)
void gemm_single(const float* __restrict__ A, const float* __restrict__ W,
                 const float* __restrict__ bias, float* __restrict__ C,
                 int N, int K)
{
    extern __shared__ float dsm[];
    gemm_pipe(A + (size_t)blockIdx.y * 128 * K,
              W + (size_t)blockIdx.x * 128 * K,
              bias + blockIdx.x * 128,
              C + (size_t)blockIdx.y * 128 * N + blockIdx.x * 128,
              N, K, dsm, 1.0f, 0);
}

// ---------------------------------------------------------------------------
// Tensor-core flash attention, cp.async double-buffered K/V raw staging.
// All inputs pre-rounded tf32 (Q also pre-scaled) -> no cvt in K/V/Q paths.
// smem (floats): Qs [0,8192), raw [8192,24576) 2 stages, Vf [24576,28672).
// ---------------------------------------------------------------------------
#define ATT_SMEM_BYTES (28672 * 4)

__global__ __launch_bounds__(256, 2)
void attn_tc_kernel(const float* __restrict__ q, const float* __restrict__ kv,
                    const float* __restrict__ mask, float* __restrict__ outp)
{
    extern __shared__ float sm[];
    float* Qs   = sm;
    float* rawp = sm + 8192;
    float* Vf   = sm + 24576;

    const int tid  = threadIdx.x;
    const int lane = tid & 31;
    const int warp = tid >> 5;
    const int qt = blockIdx.x, h = blockIdx.y, b = blockIdx.z;
    const int q0 = qt * 128;

    const unsigned raw_s = (unsigned)__cvta_generic_to_shared(rawp);

    // ---- stage Q (already tf32-rounded + scaled; pure permute) ----
    {
        const float* qbase = q + (size_t)(b * SEQ + q0) * D_MODEL + h * HEAD_DIM;
        #pragma unroll
        for (int i = 0; i < 8; i++) {
            int idx = tid + i * 256;
            int row = idx >> 4;
            int c0  = (idx & 15) << 2;
            float4 v = *(const float4*)(qbase + (size_t)row * D_MODEL + c0);
            int w  = row >> 4;
            int r  = row & 15;
            int kk = c0 >> 3;
            int j  = ((r >> 3) & 1) | ((c0 & 4) ? 2 : 0);
            int l0 = (r & 7) << 2;
            int base = ((w * 8 + kk) * 32) * 4 + j;
            Qs[base + (((l0 + 0) ^ kk) << 2)] = v.x;
            Qs[base + (((l0 + 1) ^ kk) << 2)] = v.y;
            Qs[base + (((l0 + 2) ^ kk) << 2)] = v.z;
            Qs[base + (((l0 + 3) ^ kk) << 2)] = v.w;
        }
    }

    float of[8][4];
    #pragma unroll
    for (int nt = 0; nt < 8; nt++)
        #pragma unroll
        for (int r = 0; r < 4; r++) of[nt][r] = 0.0f;
    float m0 = -1e30f, m8 = -1e30f, l0s = 0.0f, l8s = 0.0f;

    const float* kvbase = kv + (size_t)(b * SEQ) * KV_DIM + h * (2 * HEAD_DIM);
    const float* mrow0  = mask + (size_t)(q0 + warp * 16 + (lane >> 2)) * SEQ
                               + ((lane & 3) << 1);

    const int srcA = (lane & 28) | ((lane & 3) >> 1);
    const int srcB = srcA | 2;
    const bool oddl = (lane & 1);

    const int crow = tid >> 5;
    const int cch  = tid & 31;

    const int k_rowb = ((lane >> 4) << 3) + (lane & 7);
    const int k_chv  = (lane >> 3) & 1;

    #pragma unroll
    for (int i = 0; i < 8; i++) {
        int row = crow + i * 8;
        int sw  = cch ^ (row & 7);
        cp16(raw_s + (row * 128 + sw * 4) * 4,
             kvbase + (size_t)row * KV_DIM + cch * 4);
    }
    cp_commit();

    for (int kt = 0; kt < SEQ / 64; kt++) {
        const int k0 = kt * 64;
        const int s  = kt & 1;

        if (kt + 1 < SEQ / 64) {
            const float* kbn = kvbase + (size_t)(k0 + 64) * KV_DIM;
            const unsigned dst = raw_s + (s ^ 1) * 32768;
            #pragma unroll
            for (int i = 0; i < 8; i++) {
                int row = crow + i * 8;
                int sw  = cch ^ (row & 7);
                cp16(dst + (row * 128 + sw * 4) * 4,
                     kbn + (size_t)row * KV_DIM + cch * 4);
            }
            cp_commit();
            asm volatile("cp.async.wait_group 1;\n" ::: "memory");
        } else {
            asm volatile("cp.async.wait_group 0;\n" ::: "memory");
        }
        __syncthreads();

        // ---- permute raw[s] V half -> Vf (pure copy; values pre-rounded) ----
        const float* rp = rawp + s * 8192;
        #pragma unroll
        for (int i = 0; i < 4; i++) {
            int idx = tid + i * 256;
            int kr  = idx >> 4;
            int c0  = (idx & 15) << 2;
            float4 w = *(const float4*)&rp[kr * 128
                          + (((16 + (c0 >> 2)) ^ (kr & 7)) << 2)];
            int kk   = kr >> 3;
            int np   = c0 >> 4;
            int slot = (((c0 >> 3) & 1) << 1) | (((kr & 7) >= 4) ? 1 : 0);
            int l0   = ((c0 & 7) << 2) + (kr & 3);
            int base = ((kk * 4 + np) * 32) * 4 + slot;
            Vf[base + (((l0 +  0) ^ kk) << 2)] = w.x;
            Vf[base + (((l0 +  4) ^ kk) << 2)] = w.y;
            Vf[base + (((l0 +  8) ^ kk) << 2)] = w.z;
            Vf[base + (((l0 + 12) ^ kk) << 2)] = w.w;
        }
        __syncthreads();

        // ---- S = Q K^T (K fragments via ldmatrix, no cvt) ----
        const unsigned kbase = raw_s + s * 32768;
        float sf[8][4];
        #pragma unroll
        for (int nt = 0; nt < 8; nt++)
            #pragma unroll
            for (int r = 0; r < 4; r++) sf[nt][r] = 0.0f;

        #pragma unroll
        for (int kk = 0; kk < 8; kk++) {
            float4 aq = *(const float4*)&Qs[((warp * 8 + kk) * 32 + (lane ^ kk)) * 4];
            unsigned a0 = __float_as_uint(aq.x), a1 = __float_as_uint(aq.y);
            unsigned a2 = __float_as_uint(aq.z), a3 = __float_as_uint(aq.w);
            const int ch = kk * 2 + k_chv;
            #pragma unroll
            for (int np = 0; np < 4; np++) {
                int row = np * 16 + k_rowb;
                unsigned kd = kbase + row * 512 + ((ch ^ (row & 7)) << 4);
                unsigned d0, d1, d2, d3;
                ldsm_x4(d0, d1, d2, d3, kd);
                mma_tf32(sf[2 * np],     a0, a1, a2, a3, d0, d1);
                mma_tf32(sf[2 * np + 1], a0, a1, a2, a3, d2, d3);
            }
        }

        // ---- mask add ----
        #pragma unroll
        for (int nt = 0; nt < 8; nt++) {
            float2 mv0 = *(const float2*)(mrow0 + k0 + nt * 8);
            float2 mv8 = *(const float2*)(mrow0 + (size_t)8 * SEQ + k0 + nt * 8);
            sf[nt][0] += mv0.x; sf[nt][1] += mv0.y;
            sf[nt][2] += mv8.x; sf[nt][3] += mv8.y;
        }

        // ---- online softmax ----
        float mx0 = -1e30f, mx8 = -1e30f;
        #pragma unroll
        for (int nt = 0; nt < 8; nt++) {
            mx0 = fmaxf(mx0, fmaxf(sf[nt][0], sf[nt][1]));
            mx8 = fmaxf(mx8, fmaxf(sf[nt][2], sf[nt][3]));
        }
        mx0 = fmaxf(mx0, __shfl_xor_sync(0xffffffffu, mx0, 1));
        mx0 = fmaxf(mx0, __shfl_xor_sync(0xffffffffu, mx0, 2));
        mx8 = fmaxf(mx8, __shfl_xor_sync(0xffffffffu, mx8, 1));
        mx8 = fmaxf(mx8, __shfl_xor_sync(0xffffffffu, mx8, 2));

        float nm0 = fmaxf(m0, mx0), nm8 = fmaxf(m8, mx8);
        float sc0 = __expf(m0 - nm0), sc8 = __expf(m8 - nm8);
        m0 = nm0; m8 = nm8;

        float rs0 = 0.0f, rs8 = 0.0f;
        #pragma unroll
        for (int nt = 0; nt < 8; nt++) {
            sf[nt][0] = __expf(sf[nt][0] - nm0); rs0 += sf[nt][0];
            sf[nt][1] = __expf(sf[nt][1] - nm0); rs0 += sf[nt][1];
            sf[nt][2] = __expf(sf[nt][2] - nm8); rs8 += sf[nt][2];
            sf[nt][3] = __expf(sf[nt][3] - nm8); rs8 += sf[nt][3];
        }
        rs0 += __shfl_xor_sync(0xffffffffu, rs0, 1);
        rs0 += __shfl_xor_sync(0xffffffffu, rs0, 2);
        rs8 += __shfl_xor_sync(0xffffffffu, rs8, 1);
        rs8 += __shfl_xor_sync(0xffffffffu, rs8, 2);
        l0s = l0s * sc0 + rs0;
        l8s = l8s * sc8 + rs8;

        #pragma unroll
        for (int nt = 0; nt < 8; nt++) {
            of[nt][0] *= sc0; of[nt][1] *= sc0;
            of[nt][2] *= sc8; of[nt][3] *= sc8;
        }

        // ---- O += P V (C-frag -> A-frag via shuffles; P needs cvt) ----
        #pragma unroll
        for (int kk = 0; kk < 8; kk++) {
            float p0 = sf[kk][0], p1 = sf[kk][1], p2 = sf[kk][2], p3 = sf[kk][3];
            float e0 = __shfl_sync(0xffffffffu, p0, srcA);
            float e1 = __shfl_sync(0xffffffffu, p1, srcA);
            float e2 = __shfl_sync(0xffffffffu, p2, srcA);
            float e3 = __shfl_sync(0xffffffffu, p3, srcA);
            float g0 = __shfl_sync(0xffffffffu, p0, srcB);
            float g1 = __shfl_sync(0xffffffffu, p1, srcB);
            float g2 = __shfl_sync(0xffffffffu, p2, srcB);
            float g3 = __shfl_sync(0xffffffffu, p3, srcB);
            unsigned a0 = f2tf(oddl ? e1 : e0);
            unsigned a1 = f2tf(oddl ? e3 : e2);
            unsigned a2 = f2tf(oddl ? g1 : g0);
            unsigned a3 = f2tf(oddl ? g3 : g2);
            #pragma unroll
            for (int np = 0; np < 4; np++) {
                float4 vf = *(const float4*)&Vf[((kk * 4 + np) * 32 + (lane ^ kk)) * 4];
                mma_tf32(of[2 * np],     a0, a1, a2, a3,
                         __float_as_uint(vf.x), __float_as_uint(vf.y));
                mma_tf32(of[2 * np + 1], a0, a1, a2, a3,
                         __float_as_uint(vf.z), __float_as_uint(vf.w));
            }
        }
        __syncthreads();
    }

    // ---- normalize + tf32-round + store (feeds O-proj A operand) ----
    float inv0 = 1.0f / l0s, inv8 = 1.0f / l8s;
    float* obase = outp + (size_t)(b * SEQ + q0 + warp * 16 + (lane >> 2)) * D_MODEL
                        + h * HEAD_DIM + ((lane & 3) << 1);
    #pragma unroll
    for (int nt = 0; nt < 8; nt++) {
        float2 r0 = make_float2(f2tff(of[nt][0] * inv0), f2tff(of[nt][1] * inv0));
        float2 r8 = make_float2(f2tff(of[nt][2] * inv8), f2tff(of[nt][3] * inv8));
        *(float2*)(obase + nt * 8)                       = r0;
        *(float2*)(obase + (size_t)8 * D_MODEL + nt * 8) = r8;
    }
}

// ---------------------------------------------------------------------------
extern "C" void kernel_launch(void* const* d_in, const int* in_sizes, int n_in,
                              void* d_out, int out_size)
{
    const float* x    = (const float*)d_in[0];
    const float* y    = (const float*)d_in[1];
    const float* mask = (const float*)d_in[2];
    const float* Wq   = (const float*)d_in[3];
    const float* bq   = (const float*)d_in[4];
    const float* Wkv  = (const float*)d_in[5];
    const float* bkv  = (const float*)d_in[6];
    const float* Wo   = (const float*)d_in[7];
    const float* bo   = (const float*)d_in[8];
    float* out = (float*)d_out;

    float *qp, *kvp, *attnp, *xrp, *yrp, *wqp, *wkvp, *wop;
    cudaGetSymbolAddress((void**)&qp,    g_q);
    cudaGetSymbolAddress((void**)&kvp,   g_kv);
    cudaGetSymbolAddress((void**)&attnp, g_attn);
    cudaGetSymbolAddress((void**)&xrp,   g_xr);
    cudaGetSymbolAddress((void**)&yrp,   g_yr);
    cudaGetSymbolAddress((void**)&wqp,   g_wq);
    cudaGetSymbolAddress((void**)&wkvp,  g_wkv);
    cudaGetSymbolAddress((void**)&wop,   g_wo);

    cudaFuncSetAttribute(gemm_proj_qkv,
                         cudaFuncAttributeMaxDynamicSharedMemorySize,
                         GEMM_SMEM_BYTES);
    cudaFuncSetAttribute(gemm_single,
                         cudaFuncAttributeMaxDynamicSharedMemorySize,
                         GEMM_SMEM_BYTES);
    cudaFuncSetAttribute(attn_tc_kernel,
                         cudaFuncAttributeMaxDynamicSharedMemorySize,
                         ATT_SMEM_BYTES);

    dim3 blk(256);

    // pre-round inputs/weights to tf32
    prep_round<<<(PREP_TOTAL4 + 255) / 256, blk>>>(
        x, y, Wq, Wkv, Wo, xrp, yrp, wqp, wkvp, wop);
    // Q and KV projections, merged (Q also pre-scaled by 1/8, outputs rounded)
    gemm_proj_qkv<<<dim3(18, M_TOT / 128), blk, GEMM_SMEM_BYTES>>>(
        xrp, yrp, wqp, bq, wkvp, bkv, qp, kvp);
    // attention
    attn_tc_kernel<<<dim3(SEQ / 128, NUM_HEADS, BATCH), blk, ATT_SMEM_BYTES>>>(
        qp, kvp, mask, attnp);
    // out = attn @ Wo^T + bo (final output NOT rounded)
    gemm_single<<<dim3(D_MODEL / 128, M_TOT / 128), blk, GEMM_SMEM_BYTES>>>(
        attnp, wop, bo, out, D_MODEL, D_MODEL);
}

// round 9
// speedup vs baseline: 1.1774x; 1.0052x over previous
#include <cuda_runtime.h>
#include <cstdint>

#define D_MODEL   768
#define KV_DIM    1536
#define NUM_HEADS 12
#define HEAD_DIM  64
#define BATCH     4
#define SEQ       2048
#define M_TOT     (BATCH * SEQ)   // 8192

#define N_X   (M_TOT * D_MODEL)
#define N_WQ  (D_MODEL * D_MODEL)
#define N_WKV (KV_DIM * D_MODEL)
#define N_WO  (D_MODEL * D_MODEL)

#define RLN2 1.44269504f

// Scratch (no allocations allowed anywhere)
__device__ float g_q[M_TOT * D_MODEL];     // tf32-rounded, pre-scaled Q (x 0.125/ln2)
__device__ float g_kv[M_TOT * KV_DIM];     // tf32-rounded KV
__device__ float g_attn[M_TOT * D_MODEL];  // tf32-rounded attention out
__device__ float g_xr[N_X];
__device__ float g_yr[N_X];
__device__ float g_wq[N_WQ];
__device__ float g_wkv[N_WKV];
__device__ float g_wo[N_WO];

// ---------------------------------------------------------------------------
// helpers
// ---------------------------------------------------------------------------
__device__ __forceinline__ unsigned f2tf(float f) {
    unsigned r;
    asm("cvt.rna.tf32.f32 %0, %1;" : "=r"(r) : "f"(f));
    return r;
}
__device__ __forceinline__ float f2tff(float f) {
    return __uint_as_float(f2tf(f));
}
__device__ __forceinline__ float ex2(float x) {
    float r;
    asm("ex2.approx.f32 %0, %1;" : "=f"(r) : "f"(x));
    return r;
}

__device__ __forceinline__ void mma_tf32(float c[4],
                                         unsigned a0, unsigned a1,
                                         unsigned a2, unsigned a3,
                                         unsigned b0, unsigned b1)
{
    asm("mma.sync.aligned.m16n8k8.row.col.f32.tf32.tf32.f32 "
        "{%0,%1,%2,%3}, {%4,%5,%6,%7}, {%8,%9}, {%0,%1,%2,%3};\n"
        : "+f"(c[0]), "+f"(c[1]), "+f"(c[2]), "+f"(c[3])
        : "r"(a0), "r"(a1), "r"(a2), "r"(a3), "r"(b0), "r"(b1));
}

__device__ __forceinline__ void cp16(unsigned saddr, const void* gptr) {
    asm volatile("cp.async.cg.shared.global [%0], [%1], 16;\n"
                 :: "r"(saddr), "l"(gptr));
}
__device__ __forceinline__ void cp_commit() {
    asm volatile("cp.async.commit_group;\n" ::: "memory");
}

__device__ __forceinline__ void ldsm_x4(unsigned& d0, unsigned& d1,
                                        unsigned& d2, unsigned& d3,
                                        unsigned saddr)
{
    asm volatile("ldmatrix.sync.aligned.m8n8.x4.shared.b16 {%0,%1,%2,%3}, [%4];\n"
                 : "=r"(d0), "=r"(d1), "=r"(d2), "=r"(d3) : "r"(saddr));
}

// ---------------------------------------------------------------------------
// Pre-round pass
// ---------------------------------------------------------------------------
#define X4   (N_X / 4)
#define WQ4  (N_WQ / 4)
#define WKV4 (N_WKV / 4)
#define PREP_TOTAL4 (2 * X4 + 2 * WQ4 + WKV4)

__global__ void prep_round(const float* __restrict__ x, const float* __restrict__ y,
                           const float* __restrict__ Wq, const float* __restrict__ Wkv,
                           const float* __restrict__ Wo,
                           float* __restrict__ xr, float* __restrict__ yr,
                           float* __restrict__ wq, float* __restrict__ wkv,
                           float* __restrict__ wo)
{
    int i = blockIdx.x * blockDim.x + threadIdx.x;
    if (i >= PREP_TOTAL4) return;
    const float* src;
    float* dst;
    int off;
    if (i < X4)                         { src = x;   dst = xr;  off = i; }
    else if (i < 2 * X4)                { src = y;   dst = yr;  off = i - X4; }
    else if (i < 2 * X4 + WQ4)          { src = Wq;  dst = wq;  off = i - 2 * X4; }
    else if (i < 2 * X4 + WQ4 + WKV4)   { src = Wkv; dst = wkv; off = i - 2 * X4 - WQ4; }
    else                                { src = Wo;  dst = wo;  off = i - 2 * X4 - WQ4 - WKV4; }
    float4 v = *(const float4*)(src + (size_t)off * 4);
    v.x = f2tff(v.x); v.y = f2tff(v.y); v.z = f2tff(v.z); v.w = f2tff(v.w);
    *(float4*)(dst + (size_t)off * 4) = v;
}

// ---------------------------------------------------------------------------
// Pipelined tf32 GEMM (unchanged from round 8)
// ---------------------------------------------------------------------------
#define GEMM_SMEM_BYTES (24576 * 4)

__device__ __forceinline__ void gemm_pipe(const float* __restrict__ Ab,
                                          const float* __restrict__ Wb,
                                          const float* __restrict__ biasp,
                                          float* __restrict__ Cb,
                                          int N, int K, float* sm,
                                          float oscale, int round_out)
{
    float* rawA = sm;
    float* rawB = sm + 12288;

    const int tid  = threadIdx.x;
    const int lane = tid & 31;
    const int warp = tid >> 5;
    const int wm   = warp & 1;
    const int wn   = warp >> 1;

    const unsigned rawA_s = (unsigned)__cvta_generic_to_shared(rawA);
    const unsigned rawB_s = (unsigned)__cvta_generic_to_shared(rawB);

    const int srow = tid >> 3;
    const int sch  = tid & 7;

    float acc[4][4][4];
    #pragma unroll
    for (int i = 0; i < 4; i++)
        #pragma unroll
        for (int j = 0; j < 4; j++)
            #pragma unroll
            for (int r = 0; r < 4; r++) acc[i][j][r] = 0.0f;

    const int ntile = K >> 5;

    const int a_row = wm * 64 + (lane & 15);
    const int a_chv = (lane >> 4);
    const int b_row = wn * 32 + ((lane >> 4) << 3) + (lane & 7);
    const int b_chv = (lane >> 3) & 1;

    #pragma unroll
    for (int i = 0; i < 4; i++) {
        int row = srow + i * 32;
        int sw  = sch ^ (row & 7);
        cp16(rawA_s + (row * 32 + sw * 4) * 4, Ab + (size_t)row * K + sch * 4);
        cp16(rawB_s + (row * 32 + sw * 4) * 4, Wb + (size_t)row * K + sch * 4);
    }
    cp_commit();
    if (1 < ntile) {
        #pragma unroll
        for (int i = 0; i < 4; i++) {
            int row = srow + i * 32;
            int sw  = sch ^ (row & 7);
            cp16(rawA_s + (4096 + row * 32 + sw * 4) * 4,
                 Ab + (size_t)row * K + 32 + sch * 4);
            cp16(rawB_s + (4096 + row * 32 + sw * 4) * 4,
                 Wb + (size_t)row * K + 32 + sch * 4);
        }
    }
    cp_commit();

    int st = 0;
    for (int t = 0; t < ntile; t++) {
        if (t + 2 < ntile) {
            const int koff = (t + 2) << 5;
            int ns = st + 2; if (ns >= 3) ns -= 3;
            #pragma unroll
            for (int i = 0; i < 4; i++) {
                int row = srow + i * 32;
                int sw  = sch ^ (row & 7);
                cp16(rawA_s + (ns * 4096 + row * 32 + sw * 4) * 4,
                     Ab + (size_t)row * K + koff + sch * 4);
                cp16(rawB_s + (ns * 4096 + row * 32 + sw * 4) * 4,
                     Wb + (size_t)row * K + koff + sch * 4);
            }
            cp_commit();
            asm volatile("cp.async.wait_group 2;\n" ::: "memory");
        } else if (t + 1 < ntile) {
            asm volatile("cp.async.wait_group 1;\n" ::: "memory");
        } else {
            asm volatile("cp.async.wait_group 0;\n" ::: "memory");
        }
        __syncthreads();

        const unsigned baseA = rawA_s + st * 16384;
        const unsigned baseB = rawB_s + st * 16384;

        #pragma unroll
        for (int kk = 0; kk < 4; kk++) {
            unsigned a[4][4], b[4][2];
            #pragma unroll
            for (int mt = 0; mt < 4; mt++) {
                int row = a_row + mt * 16;
                int ch  = kk * 2 + a_chv;
                unsigned ad = baseA + row * 128 + ((ch ^ (row & 7)) << 4);
                ldsm_x4(a[mt][0], a[mt][1], a[mt][2], a[mt][3], ad);
            }
            #pragma unroll
            for (int p = 0; p < 2; p++) {
                int row = b_row + p * 16;
                int ch  = kk * 2 + b_chv;
                unsigned bd = baseB + row * 128 + ((ch ^ (row & 7)) << 4);
                ldsm_x4(b[2 * p][0], b[2 * p][1], b[2 * p + 1][0], b[2 * p + 1][1], bd);
            }
            #pragma unroll
            for (int mt = 0; mt < 4; mt++)
                #pragma unroll
                for (int nt = 0; nt < 4; nt++)
                    mma_tf32(acc[mt][nt], a[mt][0], a[mt][1], a[mt][2], a[mt][3],
                             b[nt][0], b[nt][1]);
        }
        __syncthreads();
        st++; if (st == 3) st = 0;
    }

    #pragma unroll
    for (int mt = 0; mt < 4; mt++) {
        int row = (wm * 4 + mt) * 16 + (lane >> 2);
        #pragma unroll
        for (int nt = 0; nt < 4; nt++) {
            int col = (wn * 4 + nt) * 8 + ((lane & 3) << 1);
            float2 bv = *(const float2*)(biasp + col);
            float2 r0, r1;
            r0.x = (acc[mt][nt][0] + bv.x) * oscale;
            r0.y = (acc[mt][nt][1] + bv.y) * oscale;
            r1.x = (acc[mt][nt][2] + bv.x) * oscale;
            r1.y = (acc[mt][nt][3] + bv.y) * oscale;
            if (round_out) {
                r0.x = f2tff(r0.x); r0.y = f2tff(r0.y);
                r1.x = f2tff(r1.x); r1.y = f2tff(r1.y);
            }
            *(float2*)(Cb + (size_t)row * N + col)       = r0;
            *(float2*)(Cb + (size_t)(row + 8) * N + col) = r1;
        }
    }
}

__global__ __launch_bounds__(256, 2)
void gemm_proj_qkv(const float* __restrict__ x, const float* __restrict__ y,
                   const float* __restrict__ Wq, const float* __restrict__ bq,
                   const float* __restrict__ Wkv, const float* __restrict__ bkv,
                   float* __restrict__ qout, float* __restrict__ kvout)
{
    extern __shared__ float dsm[];
    const int bx = blockIdx.x, by = blockIdx.y;
    if (bx < 6) {
        gemm_pipe(x + (size_t)by * 128 * D_MODEL,
                  Wq + (size_t)bx * 128 * D_MODEL,
                  bq + bx * 128,
                  qout + (size_t)by * 128 * D_MODEL + bx * 128,
                  D_MODEL, D_MODEL, dsm, 0.125f * RLN2, 1);
    } else {
        const int cx = bx - 6;
        gemm_pipe(y + (size_t)by * 128 * D_MODEL,
                  Wkv + (size_t)cx * 128 * D_MODEL,
                  bkv + cx * 128,
                  kvout + (size_t)by * 128 * KV_DIM + cx * 128,
                  KV_DIM, D_MODEL, dsm, 1.0f, 1);
    }
}

__global__ __launch_bounds__(256, 2)
void gemm_single(const float* __restrict__ A, const float* __restrict__ W,
                 const float* __restrict__ bias, float* __restrict__ C,
                 int N, int K)
{
    extern __shared__ float dsm[];
    gemm_pipe(A + (size_t)blockIdx.y * 128 * K,
              W + (size_t)blockIdx.x * 128 * K,
              bias + blockIdx.x * 128,
              C + (size_t)blockIdx.y * 128 * N + blockIdx.x * 128,
              N, K, dsm, 1.0f, 0);
}

// ---------------------------------------------------------------------------
// Flash attention v2: 128 threads = 4 warps, 32 queries/warp (two 16-row
// stripes SHARING each K/V fragment load) -> operand smem reads halved.
// Softmax in log2 domain (Q pre-scaled by 0.125/ln2 in GEMM; mask scaled
// by 1/ln2 at load; ex2.approx).
// smem (floats): Qs [0,8192), raw [8192,24576) 2 stages, Vf [24576,28672).
// ---------------------------------------------------------------------------
#define ATT_SMEM_BYTES (28672 * 4)

__global__ __launch_bounds__(128, 2)
void attn_tc_kernel(const float* __restrict__ q, const float* __restrict__ kv,
                    const float* __restrict__ mask, float* __restrict__ outp)
{
    extern __shared__ float sm[];
    float* Qs   = sm;
    float* rawp = sm + 8192;
    float* Vf   = sm + 24576;

    const int tid  = threadIdx.x;
    const int lane = tid & 31;
    const int warp = tid >> 5;          // 0..3
    const int qt = blockIdx.x, h = blockIdx.y, b = blockIdx.z;
    const int q0 = qt * 128;

    const unsigned raw_s = (unsigned)__cvta_generic_to_shared(rawp);

    // ---- stage Q (pre-rounded + pre-scaled; pure permute) ----
    {
        const float* qbase = q + (size_t)(b * SEQ + q0) * D_MODEL + h * HEAD_DIM;
        #pragma unroll
        for (int i = 0; i < 16; i++) {
            int idx = tid + i * 128;
            int row = idx >> 4;
            int c0  = (idx & 15) << 2;
            float4 v = *(const float4*)(qbase + (size_t)row * D_MODEL + c0);
            int w  = row >> 4;               // stripe index 0..7
            int r  = row & 15;
            int kk = c0 >> 3;
            int j  = ((r >> 3) & 1) | ((c0 & 4) ? 2 : 0);
            int l0 = (r & 7) << 2;
            int base = ((w * 8 + kk) * 32) * 4 + j;
            Qs[base + (((l0 + 0) ^ kk) << 2)] = v.x;
            Qs[base + (((l0 + 1) ^ kk) << 2)] = v.y;
            Qs[base + (((l0 + 2) ^ kk) << 2)] = v.z;
            Qs[base + (((l0 + 3) ^ kk) << 2)] = v.w;
        }
    }

    float of[2][8][4];
    #pragma unroll
    for (int st = 0; st < 2; st++)
        #pragma unroll
        for (int nt = 0; nt < 8; nt++)
            #pragma unroll
            for (int r = 0; r < 4; r++) of[st][nt][r] = 0.0f;
    float mS[2][2], lS[2][2];
    #pragma unroll
    for (int st = 0; st < 2; st++) {
        mS[st][0] = mS[st][1] = -1e30f;
        lS[st][0] = lS[st][1] = 0.0f;
    }

    const float* kvbase = kv + (size_t)(b * SEQ) * KV_DIM + h * (2 * HEAD_DIM);
    const float* mrow[2];
    mrow[0] = mask + (size_t)(q0 + warp * 32 + (lane >> 2)) * SEQ + ((lane & 3) << 1);
    mrow[1] = mrow[0] + (size_t)16 * SEQ;

    const int srcA = (lane & 28) | ((lane & 3) >> 1);
    const int srcB = srcA | 2;
    const bool oddl = (lane & 1);

    const int k_rowb = ((lane >> 4) << 3) + (lane & 7);
    const int k_chv  = (lane >> 3) & 1;

    // prologue: stage tile 0 (2048 16B-chunks, 128 threads -> 16 each)
    #pragma unroll
    for (int i = 0; i < 16; i++) {
        int idx = tid + i * 128;
        int row = idx >> 5;
        int ch  = idx & 31;
        int sw  = ch ^ (row & 7);
        cp16(raw_s + (row * 128 + sw * 4) * 4,
             kvbase + (size_t)row * KV_DIM + ch * 4);
    }
    cp_commit();

    for (int kt = 0; kt < SEQ / 64; kt++) {
        const int k0 = kt * 64;
        const int s  = kt & 1;

        if (kt + 1 < SEQ / 64) {
            const float* kbn = kvbase + (size_t)(k0 + 64) * KV_DIM;
            const unsigned dst = raw_s + (s ^ 1) * 32768;
            #pragma unroll
            for (int i = 0; i < 16; i++) {
                int idx = tid + i * 128;
                int row = idx >> 5;
                int ch  = idx & 31;
                int sw  = ch ^ (row & 7);
                cp16(dst + (row * 128 + sw * 4) * 4,
                     kbn + (size_t)row * KV_DIM + ch * 4);
            }
            cp_commit();
            asm volatile("cp.async.wait_group 1;\n" ::: "memory");
        } else {
            asm volatile("cp.async.wait_group 0;\n" ::: "memory");
        }
        __syncthreads();

        // ---- permute raw[s] V half -> Vf ----
        const float* rp = rawp + s * 8192;
        #pragma unroll
        for (int i = 0; i < 8; i++) {
            int idx = tid + i * 128;
            int kr  = idx >> 4;
            int c0  = (idx & 15) << 2;
            float4 w = *(const float4*)&rp[kr * 128
                          + (((16 + (c0 >> 2)) ^ (kr & 7)) << 2)];
            int kk   = kr >> 3;
            int np   = c0 >> 4;
            int slot = (((c0 >> 3) & 1) << 1) | (((kr & 7) >= 4) ? 1 : 0);
            int l0   = ((c0 & 7) << 2) + (kr & 3);
            int base = ((kk * 4 + np) * 32) * 4 + slot;
            Vf[base + (((l0 +  0) ^ kk) << 2)] = w.x;
            Vf[base + (((l0 +  4) ^ kk) << 2)] = w.y;
            Vf[base + (((l0 +  8) ^ kk) << 2)] = w.z;
            Vf[base + (((l0 + 12) ^ kk) << 2)] = w.w;
        }
        __syncthreads();

        // ---- S = Q K^T : K fragments shared by both stripes ----
        const unsigned kbase = raw_s + s * 32768;
        float sf[2][8][4];
        #pragma unroll
        for (int st = 0; st < 2; st++)
            #pragma unroll
            for (int nt = 0; nt < 8; nt++)
                #pragma unroll
                for (int r = 0; r < 4; r++) sf[st][nt][r] = 0.0f;

        #pragma unroll
        for (int kk = 0; kk < 8; kk++) {
            float4 aq0 = *(const float4*)&Qs[(((warp * 2 + 0) * 8 + kk) * 32 + (lane ^ kk)) * 4];
            float4 aq1 = *(const float4*)&Qs[(((warp * 2 + 1) * 8 + kk) * 32 + (lane ^ kk)) * 4];
            unsigned a00 = __float_as_uint(aq0.x), a01 = __float_as_uint(aq0.y);
            unsigned a02 = __float_as_uint(aq0.z), a03 = __float_as_uint(aq0.w);
            unsigned a10 = __float_as_uint(aq1.x), a11 = __float_as_uint(aq1.y);
            unsigned a12 = __float_as_uint(aq1.z), a13 = __float_as_uint(aq1.w);
            const int ch = kk * 2 + k_chv;
            #pragma unroll
            for (int np = 0; np < 4; np++) {
                int row = np * 16 + k_rowb;
                unsigned kd = kbase + row * 512 + ((ch ^ (row & 7)) << 4);
                unsigned d0, d1, d2, d3;
                ldsm_x4(d0, d1, d2, d3, kd);
                mma_tf32(sf[0][2 * np],     a00, a01, a02, a03, d0, d1);
                mma_tf32(sf[0][2 * np + 1], a00, a01, a02, a03, d2, d3);
                mma_tf32(sf[1][2 * np],     a10, a11, a12, a13, d0, d1);
                mma_tf32(sf[1][2 * np + 1], a10, a11, a12, a13, d2, d3);
            }
        }

        // ---- mask + online softmax (log2 domain), per stripe ----
        #pragma unroll
        for (int st = 0; st < 2; st++) {
            #pragma unroll
            for (int nt = 0; nt < 8; nt++) {
                float2 mv0 = *(const float2*)(mrow[st] + k0 + nt * 8);
                float2 mv8 = *(const float2*)(mrow[st] + (size_t)8 * SEQ + k0 + nt * 8);
                sf[st][nt][0] = fmaf(mv0.x, RLN2, sf[st][nt][0]);
                sf[st][nt][1] = fmaf(mv0.y, RLN2, sf[st][nt][1]);
                sf[st][nt][2] = fmaf(mv8.x, RLN2, sf[st][nt][2]);
                sf[st][nt][3] = fmaf(mv8.y, RLN2, sf[st][nt][3]);
            }
            float mx0 = -1e30f, mx8 = -1e30f;
            #pragma unroll
            for (int nt = 0; nt < 8; nt++) {
                mx0 = fmaxf(mx0, fmaxf(sf[st][nt][0], sf[st][nt][1]));
                mx8 = fmaxf(mx8, fmaxf(sf[st][nt][2], sf[st][nt][3]));
            }
            mx0 = fmaxf(mx0, __shfl_xor_sync(0xffffffffu, mx0, 1));
            mx0 = fmaxf(mx0, __shfl_xor_sync(0xffffffffu, mx0, 2));
            mx8 = fmaxf(mx8, __shfl_xor_sync(0xffffffffu, mx8, 1));
            mx8 = fmaxf(mx8, __shfl_xor_sync(0xffffffffu, mx8, 2));

            float nm0 = fmaxf(mS[st][0], mx0), nm8 = fmaxf(mS[st][1], mx8);
            float sc0 = ex2(mS[st][0] - nm0), sc8 = ex2(mS[st][1] - nm8);
            mS[st][0] = nm0; mS[st][1] = nm8;

            float rs0 = 0.0f, rs8 = 0.0f;
            #pragma unroll
            for (int nt = 0; nt < 8; nt++) {
                sf[st][nt][0] = ex2(sf[st][nt][0] - nm0); rs0 += sf[st][nt][0];
                sf[st][nt][1] = ex2(sf[st][nt][1] - nm0); rs0 += sf[st][nt][1];
                sf[st][nt][2] = ex2(sf[st][nt][2] - nm8); rs8 += sf[st][nt][2];
                sf[st][nt][3] = ex2(sf[st][nt][3] - nm8); rs8 += sf[st][nt][3];
            }
            rs0 += __shfl_xor_sync(0xffffffffu, rs0, 1);
            rs0 += __shfl_xor_sync(0xffffffffu, rs0, 2);
            rs8 += __shfl_xor_sync(0xffffffffu, rs8, 1);
            rs8 += __shfl_xor_sync(0xffffffffu, rs8, 2);
            lS[st][0] = lS[st][0] * sc0 + rs0;
            lS[st][1] = lS[st][1] * sc8 + rs8;

            #pragma unroll
            for (int nt = 0; nt < 8; nt++) {
                of[st][nt][0] *= sc0; of[st][nt][1] *= sc0;
                of[st][nt][2] *= sc8; of[st][nt][3] *= sc8;
            }
        }

        // ---- O += P V : V fragments shared by both stripes ----
        #pragma unroll
        for (int kk = 0; kk < 8; kk++) {
            unsigned ap[2][4];
            #pragma unroll
            for (int st = 0; st < 2; st++) {
                float p0 = sf[st][kk][0], p1 = sf[st][kk][1];
                float p2 = sf[st][kk][2], p3 = sf[st][kk][3];
                float e0 = __shfl_sync(0xffffffffu, p0, srcA);
                float e1 = __shfl_sync(0xffffffffu, p1, srcA);
                float e2 = __shfl_sync(0xffffffffu, p2, srcA);
                float e3 = __shfl_sync(0xffffffffu, p3, srcA);
                float g0 = __shfl_sync(0xffffffffu, p0, srcB);
                float g1 = __shfl_sync(0xffffffffu, p1, srcB);
                float g2 = __shfl_sync(0xffffffffu, p2, srcB);
                float g3 = __shfl_sync(0xffffffffu, p3, srcB);
                ap[st][0] = f2tf(oddl ? e1 : e0);
                ap[st][1] = f2tf(oddl ? e3 : e2);
                ap[st][2] = f2tf(oddl ? g1 : g0);
                ap[st][3] = f2tf(oddl ? g3 : g2);
            }
            #pragma unroll
            for (int np = 0; np < 4; np++) {
                float4 vf = *(const float4*)&Vf[((kk * 4 + np) * 32 + (lane ^ kk)) * 4];
                unsigned v0 = __float_as_uint(vf.x), v1 = __float_as_uint(vf.y);
                unsigned v2 = __float_as_uint(vf.z), v3 = __float_as_uint(vf.w);
                mma_tf32(of[0][2 * np],     ap[0][0], ap[0][1], ap[0][2], ap[0][3], v0, v1);
                mma_tf32(of[0][2 * np + 1], ap[0][0], ap[0][1], ap[0][2], ap[0][3], v2, v3);
                mma_tf32(of[1][2 * np],     ap[1][0], ap[1][1], ap[1][2], ap[1][3], v0, v1);
                mma_tf32(of[1][2 * np + 1], ap[1][0], ap[1][1], ap[1][2], ap[1][3], v2, v3);
            }
        }
        __syncthreads();
    }

    // ---- normalize + tf32-round + store both stripes ----
    #pragma unroll
    for (int st = 0; st < 2; st++) {
        float inv0 = 1.0f / lS[st][0], inv8 = 1.0f / lS[st][1];
        float* obase = outp + (size_t)(b * SEQ + q0 + warp * 32 + st * 16
                                       + (lane >> 2)) * D_MODEL
                            + h * HEAD_DIM + ((lane & 3) << 1);
        #pragma unroll
        for (int nt = 0; nt < 8; nt++) {
            float2 r0 = make_float2(f2tff(of[st][nt][0] * inv0),
                                    f2tff(of[st][nt][1] * inv0));
            float2 r8 = make_float2(f2tff(of[st][nt][2] * inv8),
                                    f2tff(of[st][nt][3] * inv8));
            *(float2*)(obase + nt * 8)                       = r0;
            *(float2*)(obase + (size_t)8 * D_MODEL + nt * 8) = r8;
        }
    }
}

// ---------------------------------------------------------------------------
extern "C" void kernel_launch(void* const* d_in, const int* in_sizes, int n_in,
                              void* d_out, int out_size)
{
    const float* x    = (const float*)d_in[0];
    const float* y    = (const float*)d_in[1];
    const float* mask = (const float*)d_in[2];
    const float* Wq   = (const float*)d_in[3];
    const float* bq   = (const float*)d_in[4];
    const float* Wkv  = (const float*)d_in[5];
    const float* bkv  = (const float*)d_in[6];
    const float* Wo   = (const float*)d_in[7];
    const float* bo   = (const float*)d_in[8];
    float* out = (float*)d_out;

    float *qp, *kvp, *attnp, *xrp, *yrp, *wqp, *wkvp, *wop;
    cudaGetSymbolAddress((void**)&qp,    g_q);
    cudaGetSymbolAddress((void**)&kvp,   g_kv);
    cudaGetSymbolAddress((void**)&attnp, g_attn);
    cudaGetSymbolAddress((void**)&xrp,   g_xr);
    cudaGetSymbolAddress((void**)&yrp,   g_yr);
    cudaGetSymbolAddress((void**)&wqp,   g_wq);
    cudaGetSymbolAddress((void**)&wkvp,  g_wkv);
    cudaGetSymbolAddress((void**)&wop,   g_wo);

    cudaFuncSetAttribute(gemm_proj_qkv,
                         cudaFuncAttributeMaxDynamicSharedMemorySize,
                         GEMM_SMEM_BYTES);
    cudaFuncSetAttribute(gemm_single,
                         cudaFuncAttributeMaxDynamicSharedMemorySize,
                         GEMM_SMEM_BYTES);
    cudaFuncSetAttribute(attn_tc_kernel,
                         cudaFuncAttributeMaxDynamicSharedMemorySize,
                         ATT_SMEM_BYTES);

    prep_round<<<(PREP_TOTAL4 + 255) / 256, 256>>>(
        x, y, Wq, Wkv, Wo, xrp, yrp, wqp, wkvp, wop);
    gemm_proj_qkv<<<dim3(18, M_TOT / 128), 256, GEMM_SMEM_BYTES>>>(
        xrp, yrp, wqp, bq, wkvp, bkv, qp, kvp);
    attn_tc_kernel<<<dim3(SEQ / 128, NUM_HEADS, BATCH), 128, ATT_SMEM_BYTES>>>(
        qp, kvp, mask, attnp);
    gemm_single<<<dim3(D_MODEL / 128, M_TOT / 128), 256, GEMM_SMEM_BYTES>>>(
        attnp, wop, bo, out, D_MODEL, D_MODEL);
}